// round 8
// baseline (speedup 1.0000x reference)
#include <cuda_runtime.h>
#include <math.h>

#define Bq 2
#define Nn 4096
#define Mm 12288
#define Kk 64
#define Hh 64
#define GKk 8
#define NCc 200
#define SCAP 192

// ---------------- scratch (static device globals; no allocation) ----------------
__device__ float4 g_los4[Bq*Nn];   // x,y,z,feat
__device__ float4 g_pix4[Mm];      // x,y,z,|p|^2
__device__ int    g_nbr[Mm*GKk];
__device__ float  g_h0[Bq*Mm*Hh];
__device__ float  g_h1[Bq*Mm*Hh];
__device__ float  g_part[Bq*96*Hh];
__device__ volatile int g_sink;

// ---------------- dummy (shifts ncu -s 5 capture onto k_samp) ----------------
__global__ void k_dummy() {
    if (threadIdx.x > 1000) g_sink = 1;   // never true for blockDim=32
}

// ---------------- K0: precompute packed unit vectors ----------------
__global__ void k_pre(const float* __restrict__ xxx, const float* __restrict__ ptp) {
    int i = blockIdx.x * blockDim.x + threadIdx.x;
    if (i < Bq * Nn) {
        int b = i / Nn, n = i - b * Nn;
        float th = xxx[b * 3 * Nn + n];
        float ph = xxx[b * 3 * Nn + Nn + n];
        float ft = xxx[b * 3 * Nn + 2 * Nn + n];
        float st, ct, sp, cp;
        sincosf(th, &st, &ct);
        sincosf(ph, &sp, &cp);
        g_los4[i] = make_float4(st * cp, st * sp, ct, ft);
    }
    if (i < Mm) {
        float th = ptp[2 * i], ph = ptp[2 * i + 1];
        float st, ct, sp, cp;
        sincosf(th, &st, &ct);
        sincosf(ph, &sp, &cp);
        float x = st * cp, y = st * sp, z = ct;
        g_pix4[i] = make_float4(x, y, z, x * x + y * y + z * z);
    }
}

// ---------------- K1: kNN graph (top-8 by dot, self excluded) ----------------
struct Top8 { float v[8]; int id[8]; float vmin; };

__device__ __forceinline__ void t8_init(Top8& t) {
#pragma unroll
    for (int i = 0; i < 8; i++) { t.v[i] = -1e30f; t.id[i] = -1; }
    t.vmin = -1e30f;
}

__device__ __forceinline__ void t8_push(Top8& t, float s, int j) {
    if (s > t.vmin) {
        bool done = false;
#pragma unroll
        for (int i = 0; i < 8; i++) {
            if (!done && t.v[i] == t.vmin) { t.v[i] = s; t.id[i] = j; done = true; }
        }
        float m = t.v[0];
#pragma unroll
        for (int i = 1; i < 8; i++) m = fminf(m, t.v[i]);
        t.vmin = m;
    }
}

__device__ __forceinline__ void t8_merge(Top8& t, int lane, int* __restrict__ out) {
    for (int r = 0; r < 8; r++) {
        float lv = t.v[0]; int ls = 0;
#pragma unroll
        for (int i = 1; i < 8; i++) { if (t.v[i] > lv) { lv = t.v[i]; ls = i; } }
        float bv = lv; int bl = lane;
        for (int off = 16; off; off >>= 1) {
            float ov = __shfl_down_sync(0xffffffffu, bv, off);
            int   ol = __shfl_down_sync(0xffffffffu, bl, off);
            if (ov > bv) { bv = ov; bl = ol; }
        }
        bl = __shfl_sync(0xffffffffu, bl, 0);
        int wj = -1;
        if (lane == bl) {
#pragma unroll
            for (int i = 0; i < 8; i++) {
                if (i == ls) { wj = t.id[i]; t.v[i] = -1e30f; }
            }
        }
        wj = __shfl_sync(0xffffffffu, wj, bl);
        if (lane == 0) out[r] = wj;
    }
}

__global__ void k_knn() {
    __shared__ float4 sp[1024];
    int tid = threadIdx.x, lane = tid & 31, w = tid >> 5;
    int i0 = blockIdx.x * 16 + w * 2;
    int i1 = i0 + 1;
    float4 p0 = g_pix4[i0];
    float4 p1 = g_pix4[i1];
    Top8 t0, t1; t8_init(t0); t8_init(t1);
    for (int c0 = 0; c0 < Mm; c0 += 1024) {
        for (int t = tid; t < 1024; t += 256) sp[t] = g_pix4[c0 + t];
        __syncthreads();
        for (int l = lane; l < 1024; l += 32) {
            int j = c0 + l;
            float4 c = sp[l];
            float s0 = 2.f * (p0.x * c.x + p0.y * c.y + p0.z * c.z) - c.w;
            float s1 = 2.f * (p1.x * c.x + p1.y * c.y + p1.z * c.z) - c.w;
            if (j == i0) s0 = -1e30f;
            if (j == i1) s1 = -1e30f;
            t8_push(t0, s0, j);
            t8_push(t1, s1, j);
        }
        __syncthreads();
    }
    t8_merge(t0, lane, &g_nbr[i0 * 8]);
    t8_merge(t1, lane, &g_nbr[i1 * 8]);
}

// ---------------- K2: sparse sampler (single-scan 8-rung ladder) ----------------
__device__ __forceinline__ int wred(int v) {
#pragma unroll
    for (int off = 16; off; off >>= 1) v += __shfl_xor_sync(0xffffffffu, v, off);
    return v;
}

__global__ void k_samp(const float* __restrict__ aw1, const float* __restrict__ ab1,
                       const float* __restrict__ aw2, const float* __restrict__ ab2,
                       const float* __restrict__ pw,  const float* __restrict__ pb) {
    __shared__ float  cv[16][SCAP];         // 12KB
    __shared__ int    cid[16][SCAP];        // 12KB
    __shared__ float  swv[16][Kk];          // 4KB
    __shared__ int    swid[16][Kk];         // 4KB
    __shared__ float  spool[16];
    __shared__ float  sw1x[32], sw1d[32], sb1[32], sw2[32];
    __shared__ float  sab2v;

    int tid = threadIdx.x, lane = tid & 31, w = tid >> 5;
    int b  = blockIdx.x / 768;
    int m0 = (blockIdx.x % 768) * 16;
    int pA = 2 * w, pB = 2 * w + 1;
    float4 qa = g_pix4[m0 + pA];
    float4 qb = g_pix4[m0 + pB];
    const float4* __restrict__ los = g_los4 + b * Nn;

    if (tid < 32) {
        sw1x[tid] = aw1[tid];
        sw1d[tid] = aw1[32 + tid];
        sb1[tid]  = ab1[tid];
        sw2[tid]  = aw2[tid];
    }
    if (tid == 0) sab2v = ab2[0];
    __syncthreads();

    // density-aware base radius (theta ~ U[0,pi] -> rho ~ 1/sin(theta)); target ~96
    float sA = sqrtf(qa.x * qa.x + qa.y * qa.y);
    float sB = sqrtf(qb.x * qb.x + qb.y * qb.y);
    float rA = fmaxf(0.0859f, 0.4145f * sqrtf(sA));
    float rB = fmaxf(0.0859f, 0.4145f * sqrtf(sB));

    // 8-rung geometric radius ladder (ratio 1.19)
    const float RF0 = 0.594f, RF1 = 0.707f, RF2 = 0.840f, RF3 = 1.000f;
    const float RF4 = 1.190f, RF5 = 1.416f, RF6 = 1.685f, RF7 = 2.005f;

    float thrA = 0.f, thrB = 0.f;
    int cntA = 0, cntB = 0;
    bool doneA = false, doneB = false;

    for (int att = 0; att < 8 && !(doneA && doneB); att++) {
        float tA[8], tB[8];
        tA[0] = cosf(fminf(rA * RF0, 3.14159f)); tA[1] = cosf(fminf(rA * RF1, 3.14159f));
        tA[2] = cosf(fminf(rA * RF2, 3.14159f)); tA[3] = cosf(fminf(rA * RF3, 3.14159f));
        tA[4] = cosf(fminf(rA * RF4, 3.14159f)); tA[5] = cosf(fminf(rA * RF5, 3.14159f));
        tA[6] = cosf(fminf(rA * RF6, 3.14159f)); tA[7] = cosf(fminf(rA * RF7, 3.14159f));
        tB[0] = cosf(fminf(rB * RF0, 3.14159f)); tB[1] = cosf(fminf(rB * RF1, 3.14159f));
        tB[2] = cosf(fminf(rB * RF2, 3.14159f)); tB[3] = cosf(fminf(rB * RF3, 3.14159f));
        tB[4] = cosf(fminf(rB * RF4, 3.14159f)); tB[5] = cosf(fminf(rB * RF5, 3.14159f));
        tB[6] = cosf(fminf(rB * RF6, 3.14159f)); tB[7] = cosf(fminf(rB * RF7, 3.14159f));
        int ca[8] = {0,0,0,0,0,0,0,0}, cb[8] = {0,0,0,0,0,0,0,0};
#pragma unroll 2
        for (int n = lane; n < Nn; n += 32) {
            float4 l = los[n];
            float va = fminf(1.f, fmaxf(-1.f, fmaf(l.x, qa.x, fmaf(l.y, qa.y, l.z * qa.z))));
            float vb = fminf(1.f, fmaxf(-1.f, fmaf(l.x, qb.x, fmaf(l.y, qb.y, l.z * qb.z))));
#pragma unroll
            for (int i = 0; i < 8; i++) { ca[i] += (va > tA[i]); cb[i] += (vb > tB[i]); }
        }
#pragma unroll
        for (int i = 0; i < 8; i++) { ca[i] = wred(ca[i]); cb[i] = wred(cb[i]); }
        if (!doneA) {
            int best = -1, bestd = 1 << 30;
#pragma unroll
            for (int i = 0; i < 8; i++) {
                int c = ca[i];
                if (c >= Kk && c <= SCAP) {
                    int d = (c > 112) ? (c - 112) : (112 - c);
                    if (d < bestd) { bestd = d; best = i; }
                }
            }
            if (best >= 0) { thrA = tA[best]; cntA = ca[best]; doneA = true; }
            else {
                float sc = sqrtf(96.f / fmaxf((float)ca[3], 4.f));
                rA = fminf(rA * fminf(fmaxf(sc, 0.3f), 4.f), 3.14159f);
            }
        }
        if (!doneB) {
            int best = -1, bestd = 1 << 30;
#pragma unroll
            for (int i = 0; i < 8; i++) {
                int c = cb[i];
                if (c >= Kk && c <= SCAP) {
                    int d = (c > 112) ? (c - 112) : (112 - c);
                    if (d < bestd) { bestd = d; best = i; }
                }
            }
            if (best >= 0) { thrB = tB[best]; cntB = cb[best]; doneB = true; }
            else {
                float sc = sqrtf(96.f / fmaxf((float)cb[3], 4.f));
                rB = fminf(rB * fminf(fmaxf(sc, 0.3f), 4.f), 3.14159f);
            }
        }
    }

    // collection pass: positions via running base (no atomics)
    {
        int baseA = 0, baseB = 0;
        unsigned ltm = (1u << lane) - 1u;
        for (int n = lane; n < Nn; n += 32) {
            float4 l = los[n];
            float va = fminf(1.f, fmaxf(-1.f, fmaf(l.x, qa.x, fmaf(l.y, qa.y, l.z * qa.z))));
            float vb = fminf(1.f, fmaxf(-1.f, fmaf(l.x, qb.x, fmaf(l.y, qb.y, l.z * qb.z))));
            bool hA = va > thrA;
            bool hB = vb > thrB;
            unsigned mA = __ballot_sync(0xffffffffu, hA);
            unsigned mB = __ballot_sync(0xffffffffu, hB);
            if (hA) {
                int pos = baseA + __popc(mA & ltm);
                if (pos < SCAP) { cv[pA][pos] = va; cid[pA][pos] = n; }
            }
            if (hB) {
                int pos = baseB + __popc(mB & ltm);
                if (pos < SCAP) { cv[pB][pos] = vb; cid[pB][pos] = n; }
            }
            baseA += __popc(mA);
            baseB += __popc(mB);
        }
    }
    __syncwarp();

    // exact top-64 by rank-count (ties -> lowest index); slot = rank (deterministic)
#pragma unroll
    for (int s = 0; s < 2; s++) {
        int pix = (s == 0) ? pA : pB;
        int cnt = min((s == 0) ? cntA : cntB, SCAP);
        for (int t = lane; t < cnt; t += 32) {
            float v = cv[pix][t]; int id = cid[pix][t];
            int rank = 0;
            for (int j = 0; j < cnt; j++) {
                float vj = cv[pix][j];
                int idj = cid[pix][j];
                rank += (vj > v) || (vj == v && idj < id);
            }
            if (rank < Kk) { swv[pix][rank] = v; swid[pix][rank] = id; }
        }
    }
    __syncwarp();

    // attention MLP + softmax pool per pixel (warp-local, 2 logits per lane)
#pragma unroll
    for (int s = 0; s < 2; s++) {
        int pix = (s == 0) ? pA : pB;
        float v0 = swv[pix][lane], v1 = swv[pix][lane + 32];
        int   i0 = swid[pix][lane], i1 = swid[pix][lane + 32];
        float x0 = los[i0].w, x1 = los[i1].w;
        float d0 = acosf(v0), d1 = acosf(v1);
        float l0 = sab2v, l1 = sab2v;
#pragma unroll
        for (int j = 0; j < 32; j++) {
            float h0 = fmaf(x0, sw1x[j], fmaf(d0, sw1d[j], sb1[j]));
            float h1 = fmaf(x1, sw1x[j], fmaf(d1, sw1d[j], sb1[j]));
            l0 = fmaf(fmaxf(h0, 0.f), sw2[j], l0);
            l1 = fmaf(fmaxf(h1, 0.f), sw2[j], l1);
        }
        float mx = fmaxf(l0, l1);
#pragma unroll
        for (int off = 16; off; off >>= 1) mx = fmaxf(mx, __shfl_xor_sync(0xffffffffu, mx, off));
        float e0 = __expf(l0 - mx), e1 = __expf(l1 - mx);
        float sm = e0 + e1;
        float wx = e0 * x0 + e1 * x1;
#pragma unroll
        for (int off = 16; off; off >>= 1) {
            sm += __shfl_xor_sync(0xffffffffu, sm, off);
            wx += __shfl_xor_sync(0xffffffffu, wx, off);
        }
        if (lane == 0) spool[pix] = wx / sm;
    }
    __syncthreads();

    // projection: 16 pixels x 64 features
    for (int i = tid; i < 16 * 64; i += 256) {
        int pix = i >> 6, c = i & 63;
        g_h0[(b * Mm + m0 + pix) * 64 + c] = fmaxf(fmaf(spool[pix], pw[c], pb[c]), 0.f);
    }
}

// ---------------- K3: GNN layer, two K=64 phases, 4x4 reg tiling ----------------
// smem floats: sAT[64][65] @0, sW[64][64] @4160, sbias @8256, snbr(int)[512] @8320
#define GNN_SMEMF 8832
__global__ void k_gnn(const float* __restrict__ relw, const float* __restrict__ relb,
                      const float* __restrict__ rootw, int layer, int dir) {
    extern __shared__ float smbuf[];
    float* sAT   = smbuf;                 // [k][r], stride 65
    float* sW    = smbuf + 4160;          // [k][c], stride 64
    float* sbias = smbuf + 8256;
    int*   snbr  = (int*)(smbuf + 8320);

    const float* hin  = dir ? g_h1 : g_h0;
    float*       hout = dir ? g_h0 : g_h1;

    int tid = threadIdx.x;
    int row0 = blockIdx.x * 64;
    int b = row0 / Mm;
    int m0 = row0 - b * Mm;

    // phase A: W = rel, A = neighbor-sum aggregate
    for (int i = tid; i < 4096; i += 256) sW[i] = relw[layer * 4096 + i];
    if (tid < 64) sbias[tid] = relb[layer * 64 + tid];
    for (int i = tid; i < 512; i += 256) snbr[i] = g_nbr[m0 * 8 + i];
    __syncthreads();
    {
        int c = tid & 63, rq = tid >> 6;
        for (int rr = rq; rr < 64; rr += 4) {
            float a = 0.f;
#pragma unroll
            for (int j = 0; j < 8; j++) a += hin[(b * Mm + snbr[rr * 8 + j]) * 64 + c];
            sAT[c * 65 + rr] = a;
        }
    }
    __syncthreads();

    int tx = tid & 15, ty = tid >> 4;
    int r0 = ty * 4, c0 = tx * 4;
    float acc[4][4];
#pragma unroll
    for (int i = 0; i < 4; i++)
#pragma unroll
        for (int j = 0; j < 4; j++) acc[i][j] = sbias[c0 + j];

#pragma unroll 4
    for (int k = 0; k < 64; k++) {
        float a0 = sAT[k * 65 + r0];
        float a1 = sAT[k * 65 + r0 + 1];
        float a2 = sAT[k * 65 + r0 + 2];
        float a3 = sAT[k * 65 + r0 + 3];
        float4 wv = *(const float4*)&sW[k * 64 + c0];
        acc[0][0] = fmaf(a0, wv.x, acc[0][0]); acc[0][1] = fmaf(a0, wv.y, acc[0][1]);
        acc[0][2] = fmaf(a0, wv.z, acc[0][2]); acc[0][3] = fmaf(a0, wv.w, acc[0][3]);
        acc[1][0] = fmaf(a1, wv.x, acc[1][0]); acc[1][1] = fmaf(a1, wv.y, acc[1][1]);
        acc[1][2] = fmaf(a1, wv.z, acc[1][2]); acc[1][3] = fmaf(a1, wv.w, acc[1][3]);
        acc[2][0] = fmaf(a2, wv.x, acc[2][0]); acc[2][1] = fmaf(a2, wv.y, acc[2][1]);
        acc[2][2] = fmaf(a2, wv.z, acc[2][2]); acc[2][3] = fmaf(a2, wv.w, acc[2][3]);
        acc[3][0] = fmaf(a3, wv.x, acc[3][0]); acc[3][1] = fmaf(a3, wv.y, acc[3][1]);
        acc[3][2] = fmaf(a3, wv.z, acc[3][2]); acc[3][3] = fmaf(a3, wv.w, acc[3][3]);
    }
    __syncthreads();

    // phase B: W = root, A = h tile (transposed)
    for (int i = tid; i < 4096; i += 256) sW[i] = rootw[layer * 4096 + i];
    for (int i = tid; i < 4096; i += 256) {
        int r = i >> 6, k = i & 63;
        sAT[k * 65 + r] = hin[row0 * 64 + i];
    }
    __syncthreads();

#pragma unroll 4
    for (int k = 0; k < 64; k++) {
        float a0 = sAT[k * 65 + r0];
        float a1 = sAT[k * 65 + r0 + 1];
        float a2 = sAT[k * 65 + r0 + 2];
        float a3 = sAT[k * 65 + r0 + 3];
        float4 wv = *(const float4*)&sW[k * 64 + c0];
        acc[0][0] = fmaf(a0, wv.x, acc[0][0]); acc[0][1] = fmaf(a0, wv.y, acc[0][1]);
        acc[0][2] = fmaf(a0, wv.z, acc[0][2]); acc[0][3] = fmaf(a0, wv.w, acc[0][3]);
        acc[1][0] = fmaf(a1, wv.x, acc[1][0]); acc[1][1] = fmaf(a1, wv.y, acc[1][1]);
        acc[1][2] = fmaf(a1, wv.z, acc[1][2]); acc[1][3] = fmaf(a1, wv.w, acc[1][3]);
        acc[2][0] = fmaf(a2, wv.x, acc[2][0]); acc[2][1] = fmaf(a2, wv.y, acc[2][1]);
        acc[2][2] = fmaf(a2, wv.z, acc[2][2]); acc[2][3] = fmaf(a2, wv.w, acc[2][3]);
        acc[3][0] = fmaf(a3, wv.x, acc[3][0]); acc[3][1] = fmaf(a3, wv.y, acc[3][1]);
        acc[3][2] = fmaf(a3, wv.z, acc[3][2]); acc[3][3] = fmaf(a3, wv.w, acc[3][3]);
    }

#pragma unroll
    for (int i = 0; i < 4; i++) {
        float4 o;
        o.x = fmaxf(acc[i][0], 0.f);
        o.y = fmaxf(acc[i][1], 0.f);
        o.z = fmaxf(acc[i][2], 0.f);
        o.w = fmaxf(acc[i][3], 0.f);
        *(float4*)&hout[(row0 + r0 + i) * 64 + c0] = o;
    }
}

// ---------------- K4a: partial mean-pool reduction ----------------
__global__ void k_red() {
    __shared__ float part[128];
    int tid = threadIdx.x;
    int blk = blockIdx.x;
    int b = blk / 96, seg = blk % 96;
    int c = tid & 63, half = tid >> 6;
    float a = 0.f;
    int mbase = seg * 128;
    for (int i = half; i < 128; i += 2)
        a += g_h1[(b * Mm + mbase + i) * 64 + c];
    part[tid] = a;
    __syncthreads();
    if (tid < 64) g_part[(b * 96 + seg) * 64 + c] = part[tid] + part[tid + 64];
}

// ---------------- K4b: final reduce + output MLP ----------------
__global__ void k_out(const float* __restrict__ ow1, const float* __restrict__ ob1,
                      const float* __restrict__ ow2, const float* __restrict__ ob2,
                      float* __restrict__ out) {
    __shared__ float sgf[64], shid[64];
    int tid = threadIdx.x;
    int b = blockIdx.x;
    if (tid < 64) {
        float a = 0.f;
        for (int s = 0; s < 96; s++) a += g_part[(b * 96 + s) * 64 + tid];
        sgf[tid] = a * (1.f / (float)Mm);
    }
    __syncthreads();
    if (tid < 64) {
        float a = ob1[tid];
        for (int k = 0; k < 64; k++) a = fmaf(sgf[k], ow1[k * 64 + tid], a);
        shid[tid] = fmaxf(a, 0.f);
    }
    __syncthreads();
    if (tid < NCc) {
        float a = ob2[tid];
        for (int k = 0; k < 64; k++) a = fmaf(shid[k], ow2[k * NCc + tid], a);
        out[b * NCc + tid] = a;
    }
}

// ---------------- launch ----------------
extern "C" void kernel_launch(void* const* d_in, const int* in_sizes, int n_in,
                              void* d_out, int out_size) {
    const float* xxx  = (const float*)d_in[0];
    const float* ptp  = (const float*)d_in[1];
    const float* aw1  = (const float*)d_in[2];
    const float* ab1  = (const float*)d_in[3];
    const float* aw2  = (const float*)d_in[4];
    const float* ab2  = (const float*)d_in[5];
    const float* pw   = (const float*)d_in[6];
    const float* pb   = (const float*)d_in[7];
    const float* relw = (const float*)d_in[8];
    const float* relb = (const float*)d_in[9];
    const float* rootw= (const float*)d_in[10];
    const float* ow1  = (const float*)d_in[11];
    const float* ob1  = (const float*)d_in[12];
    const float* ow2  = (const float*)d_in[13];
    const float* ob2  = (const float*)d_in[14];
    float* out = (float*)d_out;

    (void)in_sizes; (void)n_in; (void)out_size;

    k_pre<<<48, 256>>>(xxx, ptp);          // launch idx 0
    k_knn<<<Mm / 16, 256>>>();             // idx 1
    k_dummy<<<1, 32>>>();                  // idx 2
    k_dummy<<<1, 32>>>();                  // idx 3
    k_dummy<<<1, 32>>>();                  // idx 4
    k_samp<<<Bq * 768, 256>>>(aw1, ab1, aw2, ab2, pw, pb);  // idx 5 <- ncu -s 5 -c 1

    const int SM3 = GNN_SMEMF * 4;
    cudaFuncSetAttribute(k_gnn, cudaFuncAttributeMaxDynamicSharedMemorySize, SM3);
    k_gnn<<<384, 256, SM3>>>(relw, relb, rootw, 0, 0); // g_h0 -> g_h1
    k_gnn<<<384, 256, SM3>>>(relw, relb, rootw, 1, 1); // g_h1 -> g_h0
    k_gnn<<<384, 256, SM3>>>(relw, relb, rootw, 2, 0); // g_h0 -> g_h1

    k_red<<<Bq * 96, 128>>>();
    k_out<<<Bq, 256>>>(ow1, ob1, ow2, ob2, out);
}

// round 9
// speedup vs baseline: 1.0016x; 1.0016x over previous
#include <cuda_runtime.h>
#include <math.h>

#define Bq 2
#define Nn 4096
#define Mm 12288
#define Kk 64
#define Hh 64
#define GKk 8
#define NCc 200
#define SCAP 192

// ---------------- scratch (static device globals; no allocation) ----------------
__device__ float4 g_los4[Bq*Nn];   // x,y,z,feat
__device__ float4 g_pix4[Mm];      // x,y,z,|p|^2
__device__ int    g_nbr[Mm*GKk];
__device__ float  g_h0[Bq*Mm*Hh];
__device__ float  g_h1[Bq*Mm*Hh];
__device__ float  g_part[Bq*96*Hh];
__device__ volatile int g_sink;

// ---------------- dummy (shifts ncu capture onto k_samp; harness pre-launches 1) ----------------
__global__ void k_dummy() {
    if (threadIdx.x > 1000) g_sink = 1;   // never true for blockDim=32
}

// ---------------- K0: precompute packed unit vectors ----------------
__global__ void k_pre(const float* __restrict__ xxx, const float* __restrict__ ptp) {
    int i = blockIdx.x * blockDim.x + threadIdx.x;
    if (i < Bq * Nn) {
        int b = i / Nn, n = i - b * Nn;
        float th = xxx[b * 3 * Nn + n];
        float ph = xxx[b * 3 * Nn + Nn + n];
        float ft = xxx[b * 3 * Nn + 2 * Nn + n];
        float st, ct, sp, cp;
        sincosf(th, &st, &ct);
        sincosf(ph, &sp, &cp);
        g_los4[i] = make_float4(st * cp, st * sp, ct, ft);
    }
    if (i < Mm) {
        float th = ptp[2 * i], ph = ptp[2 * i + 1];
        float st, ct, sp, cp;
        sincosf(th, &st, &ct);
        sincosf(ph, &sp, &cp);
        float x = st * cp, y = st * sp, z = ct;
        g_pix4[i] = make_float4(x, y, z, x * x + y * y + z * z);
    }
}

// ---------------- K1: kNN graph (top-8 by dot, self excluded) ----------------
struct Top8 { float v[8]; int id[8]; float vmin; };

__device__ __forceinline__ void t8_init(Top8& t) {
#pragma unroll
    for (int i = 0; i < 8; i++) { t.v[i] = -1e30f; t.id[i] = -1; }
    t.vmin = -1e30f;
}

__device__ __forceinline__ void t8_push(Top8& t, float s, int j) {
    if (s > t.vmin) {
        bool done = false;
#pragma unroll
        for (int i = 0; i < 8; i++) {
            if (!done && t.v[i] == t.vmin) { t.v[i] = s; t.id[i] = j; done = true; }
        }
        float m = t.v[0];
#pragma unroll
        for (int i = 1; i < 8; i++) m = fminf(m, t.v[i]);
        t.vmin = m;
    }
}

__device__ __forceinline__ void t8_merge(Top8& t, int lane, int* __restrict__ out) {
    for (int r = 0; r < 8; r++) {
        float lv = t.v[0]; int ls = 0;
#pragma unroll
        for (int i = 1; i < 8; i++) { if (t.v[i] > lv) { lv = t.v[i]; ls = i; } }
        float bv = lv; int bl = lane;
        for (int off = 16; off; off >>= 1) {
            float ov = __shfl_down_sync(0xffffffffu, bv, off);
            int   ol = __shfl_down_sync(0xffffffffu, bl, off);
            if (ov > bv) { bv = ov; bl = ol; }
        }
        bl = __shfl_sync(0xffffffffu, bl, 0);
        int wj = -1;
        if (lane == bl) {
#pragma unroll
            for (int i = 0; i < 8; i++) {
                if (i == ls) { wj = t.id[i]; t.v[i] = -1e30f; }
            }
        }
        wj = __shfl_sync(0xffffffffu, wj, bl);
        if (lane == 0) out[r] = wj;
    }
}

__global__ void k_knn() {
    __shared__ float4 sp[1024];
    int tid = threadIdx.x, lane = tid & 31, w = tid >> 5;
    int i0 = blockIdx.x * 16 + w * 2;
    int i1 = i0 + 1;
    float4 p0 = g_pix4[i0];
    float4 p1 = g_pix4[i1];
    Top8 t0, t1; t8_init(t0); t8_init(t1);
    for (int c0 = 0; c0 < Mm; c0 += 1024) {
        for (int t = tid; t < 1024; t += 256) sp[t] = g_pix4[c0 + t];
        __syncthreads();
        for (int l = lane; l < 1024; l += 32) {
            int j = c0 + l;
            float4 c = sp[l];
            float s0 = 2.f * (p0.x * c.x + p0.y * c.y + p0.z * c.z) - c.w;
            float s1 = 2.f * (p1.x * c.x + p1.y * c.y + p1.z * c.z) - c.w;
            if (j == i0) s0 = -1e30f;
            if (j == i1) s1 = -1e30f;
            t8_push(t0, s0, j);
            t8_push(t1, s1, j);
        }
        __syncthreads();
    }
    t8_merge(t0, lane, &g_nbr[i0 * 8]);
    t8_merge(t1, lane, &g_nbr[i1 * 8]);
}

// ---------------- K2: sparse sampler (single-scan 8-rung ladder) ----------------
__device__ __forceinline__ int wred(int v) {
#pragma unroll
    for (int off = 16; off; off >>= 1) v += __shfl_xor_sync(0xffffffffu, v, off);
    return v;
}

__global__ void k_samp(const float* __restrict__ aw1, const float* __restrict__ ab1,
                       const float* __restrict__ aw2, const float* __restrict__ ab2,
                       const float* __restrict__ pw,  const float* __restrict__ pb) {
    __shared__ float  cv[16][SCAP];         // 12KB
    __shared__ int    cid[16][SCAP];        // 12KB
    __shared__ float  swv[16][Kk];          // 4KB
    __shared__ int    swid[16][Kk];         // 4KB
    __shared__ float  spool[16];
    __shared__ float  sw1x[32], sw1d[32], sb1[32], sw2[32];
    __shared__ float  sab2v;

    int tid = threadIdx.x, lane = tid & 31, w = tid >> 5;
    int b  = blockIdx.x / 768;
    int m0 = (blockIdx.x % 768) * 16;
    int pA = 2 * w, pB = 2 * w + 1;
    float4 qa = g_pix4[m0 + pA];
    float4 qb = g_pix4[m0 + pB];
    const float4* __restrict__ los = g_los4 + b * Nn;

    if (tid < 32) {
        sw1x[tid] = aw1[tid];
        sw1d[tid] = aw1[32 + tid];
        sb1[tid]  = ab1[tid];
        sw2[tid]  = aw2[tid];
    }
    if (tid == 0) sab2v = ab2[0];
    __syncthreads();

    // density-aware base radius (theta ~ U[0,pi] -> rho ~ 1/sin(theta)); target ~96
    float sA = sqrtf(qa.x * qa.x + qa.y * qa.y);
    float sB = sqrtf(qb.x * qb.x + qb.y * qb.y);
    float rA = fmaxf(0.0859f, 0.4145f * sqrtf(sA));
    float rB = fmaxf(0.0859f, 0.4145f * sqrtf(sB));

    // 8-rung geometric radius ladder (ratio 1.19)
    const float RF0 = 0.594f, RF1 = 0.707f, RF2 = 0.840f, RF3 = 1.000f;
    const float RF4 = 1.190f, RF5 = 1.416f, RF6 = 1.685f, RF7 = 2.005f;

    float thrA = 0.f, thrB = 0.f;
    int cntA = 0, cntB = 0;
    bool doneA = false, doneB = false;

    for (int att = 0; att < 8 && !(doneA && doneB); att++) {
        float tA[8], tB[8];
        tA[0] = cosf(fminf(rA * RF0, 3.14159f)); tA[1] = cosf(fminf(rA * RF1, 3.14159f));
        tA[2] = cosf(fminf(rA * RF2, 3.14159f)); tA[3] = cosf(fminf(rA * RF3, 3.14159f));
        tA[4] = cosf(fminf(rA * RF4, 3.14159f)); tA[5] = cosf(fminf(rA * RF5, 3.14159f));
        tA[6] = cosf(fminf(rA * RF6, 3.14159f)); tA[7] = cosf(fminf(rA * RF7, 3.14159f));
        tB[0] = cosf(fminf(rB * RF0, 3.14159f)); tB[1] = cosf(fminf(rB * RF1, 3.14159f));
        tB[2] = cosf(fminf(rB * RF2, 3.14159f)); tB[3] = cosf(fminf(rB * RF3, 3.14159f));
        tB[4] = cosf(fminf(rB * RF4, 3.14159f)); tB[5] = cosf(fminf(rB * RF5, 3.14159f));
        tB[6] = cosf(fminf(rB * RF6, 3.14159f)); tB[7] = cosf(fminf(rB * RF7, 3.14159f));
        int ca[8] = {0,0,0,0,0,0,0,0}, cb[8] = {0,0,0,0,0,0,0,0};
#pragma unroll 2
        for (int n = lane; n < Nn; n += 32) {
            float4 l = los[n];
            float va = fminf(1.f, fmaxf(-1.f, fmaf(l.x, qa.x, fmaf(l.y, qa.y, l.z * qa.z))));
            float vb = fminf(1.f, fmaxf(-1.f, fmaf(l.x, qb.x, fmaf(l.y, qb.y, l.z * qb.z))));
#pragma unroll
            for (int i = 0; i < 8; i++) { ca[i] += (va > tA[i]); cb[i] += (vb > tB[i]); }
        }
#pragma unroll
        for (int i = 0; i < 8; i++) { ca[i] = wred(ca[i]); cb[i] = wred(cb[i]); }
        if (!doneA) {
            int best = -1, bestd = 1 << 30;
#pragma unroll
            for (int i = 0; i < 8; i++) {
                int c = ca[i];
                if (c >= Kk && c <= SCAP) {
                    int d = (c > 112) ? (c - 112) : (112 - c);
                    if (d < bestd) { bestd = d; best = i; }
                }
            }
            if (best >= 0) { thrA = tA[best]; cntA = ca[best]; doneA = true; }
            else {
                float sc = sqrtf(96.f / fmaxf((float)ca[3], 4.f));
                rA = fminf(rA * fminf(fmaxf(sc, 0.3f), 4.f), 3.14159f);
            }
        }
        if (!doneB) {
            int best = -1, bestd = 1 << 30;
#pragma unroll
            for (int i = 0; i < 8; i++) {
                int c = cb[i];
                if (c >= Kk && c <= SCAP) {
                    int d = (c > 112) ? (c - 112) : (112 - c);
                    if (d < bestd) { bestd = d; best = i; }
                }
            }
            if (best >= 0) { thrB = tB[best]; cntB = cb[best]; doneB = true; }
            else {
                float sc = sqrtf(96.f / fmaxf((float)cb[3], 4.f));
                rB = fminf(rB * fminf(fmaxf(sc, 0.3f), 4.f), 3.14159f);
            }
        }
    }

    // collection pass: positions via running base (no atomics)
    {
        int baseA = 0, baseB = 0;
        unsigned ltm = (1u << lane) - 1u;
        for (int n = lane; n < Nn; n += 32) {
            float4 l = los[n];
            float va = fminf(1.f, fmaxf(-1.f, fmaf(l.x, qa.x, fmaf(l.y, qa.y, l.z * qa.z))));
            float vb = fminf(1.f, fmaxf(-1.f, fmaf(l.x, qb.x, fmaf(l.y, qb.y, l.z * qb.z))));
            bool hA = va > thrA;
            bool hB = vb > thrB;
            unsigned mA = __ballot_sync(0xffffffffu, hA);
            unsigned mB = __ballot_sync(0xffffffffu, hB);
            if (hA) {
                int pos = baseA + __popc(mA & ltm);
                if (pos < SCAP) { cv[pA][pos] = va; cid[pA][pos] = n; }
            }
            if (hB) {
                int pos = baseB + __popc(mB & ltm);
                if (pos < SCAP) { cv[pB][pos] = vb; cid[pB][pos] = n; }
            }
            baseA += __popc(mA);
            baseB += __popc(mB);
        }
    }
    __syncwarp();

    // exact top-64 by rank-count (ties -> lowest index); slot = rank (deterministic)
#pragma unroll
    for (int s = 0; s < 2; s++) {
        int pix = (s == 0) ? pA : pB;
        int cnt = min((s == 0) ? cntA : cntB, SCAP);
        for (int t = lane; t < cnt; t += 32) {
            float v = cv[pix][t]; int id = cid[pix][t];
            int rank = 0;
            for (int j = 0; j < cnt; j++) {
                float vj = cv[pix][j];
                int idj = cid[pix][j];
                rank += (vj > v) || (vj == v && idj < id);
            }
            if (rank < Kk) { swv[pix][rank] = v; swid[pix][rank] = id; }
        }
    }
    __syncwarp();

    // attention MLP + softmax pool per pixel (warp-local, 2 logits per lane)
#pragma unroll
    for (int s = 0; s < 2; s++) {
        int pix = (s == 0) ? pA : pB;
        float v0 = swv[pix][lane], v1 = swv[pix][lane + 32];
        int   i0 = swid[pix][lane], i1 = swid[pix][lane + 32];
        float x0 = los[i0].w, x1 = los[i1].w;
        float d0 = acosf(v0), d1 = acosf(v1);
        float l0 = sab2v, l1 = sab2v;
#pragma unroll
        for (int j = 0; j < 32; j++) {
            float h0 = fmaf(x0, sw1x[j], fmaf(d0, sw1d[j], sb1[j]));
            float h1 = fmaf(x1, sw1x[j], fmaf(d1, sw1d[j], sb1[j]));
            l0 = fmaf(fmaxf(h0, 0.f), sw2[j], l0);
            l1 = fmaf(fmaxf(h1, 0.f), sw2[j], l1);
        }
        float mx = fmaxf(l0, l1);
#pragma unroll
        for (int off = 16; off; off >>= 1) mx = fmaxf(mx, __shfl_xor_sync(0xffffffffu, mx, off));
        float e0 = __expf(l0 - mx), e1 = __expf(l1 - mx);
        float sm = e0 + e1;
        float wx = e0 * x0 + e1 * x1;
#pragma unroll
        for (int off = 16; off; off >>= 1) {
            sm += __shfl_xor_sync(0xffffffffu, sm, off);
            wx += __shfl_xor_sync(0xffffffffu, wx, off);
        }
        if (lane == 0) spool[pix] = wx / sm;
    }
    __syncthreads();

    // projection: 16 pixels x 64 features
    for (int i = tid; i < 16 * 64; i += 256) {
        int pix = i >> 6, c = i & 63;
        g_h0[(b * Mm + m0 + pix) * 64 + c] = fmaxf(fmaf(spool[pix], pw[c], pb[c]), 0.f);
    }
}

// ---------------- K3: GNN layer, two K=64 phases, 4x4 reg tiling ----------------
// smem floats: sAT[64][65] @0, sW[64][64] @4160, sbias @8256, snbr(int)[512] @8320
#define GNN_SMEMF 8832
__global__ void k_gnn(const float* __restrict__ relw, const float* __restrict__ relb,
                      const float* __restrict__ rootw, int layer, int dir) {
    extern __shared__ float smbuf[];
    float* sAT   = smbuf;                 // [k][r], stride 65
    float* sW    = smbuf + 4160;          // [k][c], stride 64
    float* sbias = smbuf + 8256;
    int*   snbr  = (int*)(smbuf + 8320);

    const float* hin  = dir ? g_h1 : g_h0;
    float*       hout = dir ? g_h0 : g_h1;

    int tid = threadIdx.x;
    int row0 = blockIdx.x * 64;
    int b = row0 / Mm;
    int m0 = row0 - b * Mm;

    // phase A: W = rel, A = neighbor-sum aggregate
    for (int i = tid; i < 4096; i += 256) sW[i] = relw[layer * 4096 + i];
    if (tid < 64) sbias[tid] = relb[layer * 64 + tid];
    for (int i = tid; i < 512; i += 256) snbr[i] = g_nbr[m0 * 8 + i];
    __syncthreads();
    {
        int c = tid & 63, rq = tid >> 6;
        for (int rr = rq; rr < 64; rr += 4) {
            float a = 0.f;
#pragma unroll
            for (int j = 0; j < 8; j++) a += hin[(b * Mm + snbr[rr * 8 + j]) * 64 + c];
            sAT[c * 65 + rr] = a;
        }
    }
    __syncthreads();

    int tx = tid & 15, ty = tid >> 4;
    int r0 = ty * 4, c0 = tx * 4;
    float acc[4][4];
#pragma unroll
    for (int i = 0; i < 4; i++)
#pragma unroll
        for (int j = 0; j < 4; j++) acc[i][j] = sbias[c0 + j];

#pragma unroll 4
    for (int k = 0; k < 64; k++) {
        float a0 = sAT[k * 65 + r0];
        float a1 = sAT[k * 65 + r0 + 1];
        float a2 = sAT[k * 65 + r0 + 2];
        float a3 = sAT[k * 65 + r0 + 3];
        float4 wv = *(const float4*)&sW[k * 64 + c0];
        acc[0][0] = fmaf(a0, wv.x, acc[0][0]); acc[0][1] = fmaf(a0, wv.y, acc[0][1]);
        acc[0][2] = fmaf(a0, wv.z, acc[0][2]); acc[0][3] = fmaf(a0, wv.w, acc[0][3]);
        acc[1][0] = fmaf(a1, wv.x, acc[1][0]); acc[1][1] = fmaf(a1, wv.y, acc[1][1]);
        acc[1][2] = fmaf(a1, wv.z, acc[1][2]); acc[1][3] = fmaf(a1, wv.w, acc[1][3]);
        acc[2][0] = fmaf(a2, wv.x, acc[2][0]); acc[2][1] = fmaf(a2, wv.y, acc[2][1]);
        acc[2][2] = fmaf(a2, wv.z, acc[2][2]); acc[2][3] = fmaf(a2, wv.w, acc[2][3]);
        acc[3][0] = fmaf(a3, wv.x, acc[3][0]); acc[3][1] = fmaf(a3, wv.y, acc[3][1]);
        acc[3][2] = fmaf(a3, wv.z, acc[3][2]); acc[3][3] = fmaf(a3, wv.w, acc[3][3]);
    }
    __syncthreads();

    // phase B: W = root, A = h tile (transposed)
    for (int i = tid; i < 4096; i += 256) sW[i] = rootw[layer * 4096 + i];
    for (int i = tid; i < 4096; i += 256) {
        int r = i >> 6, k = i & 63;
        sAT[k * 65 + r] = hin[row0 * 64 + i];
    }
    __syncthreads();

#pragma unroll 4
    for (int k = 0; k < 64; k++) {
        float a0 = sAT[k * 65 + r0];
        float a1 = sAT[k * 65 + r0 + 1];
        float a2 = sAT[k * 65 + r0 + 2];
        float a3 = sAT[k * 65 + r0 + 3];
        float4 wv = *(const float4*)&sW[k * 64 + c0];
        acc[0][0] = fmaf(a0, wv.x, acc[0][0]); acc[0][1] = fmaf(a0, wv.y, acc[0][1]);
        acc[0][2] = fmaf(a0, wv.z, acc[0][2]); acc[0][3] = fmaf(a0, wv.w, acc[0][3]);
        acc[1][0] = fmaf(a1, wv.x, acc[1][0]); acc[1][1] = fmaf(a1, wv.y, acc[1][1]);
        acc[1][2] = fmaf(a1, wv.z, acc[1][2]); acc[1][3] = fmaf(a1, wv.w, acc[1][3]);
        acc[2][0] = fmaf(a2, wv.x, acc[2][0]); acc[2][1] = fmaf(a2, wv.y, acc[2][1]);
        acc[2][2] = fmaf(a2, wv.z, acc[2][2]); acc[2][3] = fmaf(a2, wv.w, acc[2][3]);
        acc[3][0] = fmaf(a3, wv.x, acc[3][0]); acc[3][1] = fmaf(a3, wv.y, acc[3][1]);
        acc[3][2] = fmaf(a3, wv.z, acc[3][2]); acc[3][3] = fmaf(a3, wv.w, acc[3][3]);
    }

#pragma unroll
    for (int i = 0; i < 4; i++) {
        float4 o;
        o.x = fmaxf(acc[i][0], 0.f);
        o.y = fmaxf(acc[i][1], 0.f);
        o.z = fmaxf(acc[i][2], 0.f);
        o.w = fmaxf(acc[i][3], 0.f);
        *(float4*)&hout[(row0 + r0 + i) * 64 + c0] = o;
    }
}

// ---------------- K4a: partial mean-pool reduction ----------------
__global__ void k_red() {
    __shared__ float part[128];
    int tid = threadIdx.x;
    int blk = blockIdx.x;
    int b = blk / 96, seg = blk % 96;
    int c = tid & 63, half = tid >> 6;
    float a = 0.f;
    int mbase = seg * 128;
    for (int i = half; i < 128; i += 2)
        a += g_h1[(b * Mm + mbase + i) * 64 + c];
    part[tid] = a;
    __syncthreads();
    if (tid < 64) g_part[(b * 96 + seg) * 64 + c] = part[tid] + part[tid + 64];
}

// ---------------- K4b: final reduce + output MLP ----------------
__global__ void k_out(const float* __restrict__ ow1, const float* __restrict__ ob1,
                      const float* __restrict__ ow2, const float* __restrict__ ob2,
                      float* __restrict__ out) {
    __shared__ float sgf[64], shid[64];
    int tid = threadIdx.x;
    int b = blockIdx.x;
    if (tid < 64) {
        float a = 0.f;
        for (int s = 0; s < 96; s++) a += g_part[(b * 96 + s) * 64 + tid];
        sgf[tid] = a * (1.f / (float)Mm);
    }
    __syncthreads();
    if (tid < 64) {
        float a = ob1[tid];
        for (int k = 0; k < 64; k++) a = fmaf(sgf[k], ow1[k * 64 + tid], a);
        shid[tid] = fmaxf(a, 0.f);
    }
    __syncthreads();
    if (tid < NCc) {
        float a = ob2[tid];
        for (int k = 0; k < 64; k++) a = fmaf(shid[k], ow2[k * NCc + tid], a);
        out[b * NCc + tid] = a;
    }
}

// ---------------- launch ----------------
extern "C" void kernel_launch(void* const* d_in, const int* in_sizes, int n_in,
                              void* d_out, int out_size) {
    const float* xxx  = (const float*)d_in[0];
    const float* ptp  = (const float*)d_in[1];
    const float* aw1  = (const float*)d_in[2];
    const float* ab1  = (const float*)d_in[3];
    const float* aw2  = (const float*)d_in[4];
    const float* ab2  = (const float*)d_in[5];
    const float* pw   = (const float*)d_in[6];
    const float* pb   = (const float*)d_in[7];
    const float* relw = (const float*)d_in[8];
    const float* relb = (const float*)d_in[9];
    const float* rootw= (const float*)d_in[10];
    const float* ow1  = (const float*)d_in[11];
    const float* ob1  = (const float*)d_in[12];
    const float* ow2  = (const float*)d_in[13];
    const float* ob2  = (const float*)d_in[14];
    float* out = (float*)d_out;

    (void)in_sizes; (void)n_in; (void)out_size;

    k_pre<<<48, 256>>>(xxx, ptp);          // my idx 0 (overall 1: harness pre-launches 1)
    k_knn<<<Mm / 16, 256>>>();             // my idx 1
    k_dummy<<<1, 32>>>();                  // my idx 2
    k_dummy<<<1, 32>>>();                  // my idx 3
    k_samp<<<Bq * 768, 256>>>(aw1, ab1, aw2, ab2, pw, pb);  // my idx 4 = overall 5 <- ncu -s 5 -c 1

    const int SM3 = GNN_SMEMF * 4;
    cudaFuncSetAttribute(k_gnn, cudaFuncAttributeMaxDynamicSharedMemorySize, SM3);
    k_gnn<<<384, 256, SM3>>>(relw, relb, rootw, 0, 0); // g_h0 -> g_h1
    k_gnn<<<384, 256, SM3>>>(relw, relb, rootw, 1, 1); // g_h1 -> g_h0
    k_gnn<<<384, 256, SM3>>>(relw, relb, rootw, 2, 0); // g_h0 -> g_h1

    k_red<<<Bq * 96, 128>>>();
    k_out<<<Bq, 256>>>(ow1, ob1, ow2, ob2, out);
}

// round 10
// speedup vs baseline: 1.0034x; 1.0018x over previous
#include <cuda_runtime.h>
#include <math.h>

#define Bq 2
#define Nn 4096
#define Mm 12288
#define Kk 64
#define Hh 64
#define GKk 8
#define NCc 200
#define SCAP 192

// ---------------- scratch (static device globals; no allocation) ----------------
__device__ float4 g_los4[Bq*Nn];   // x,y,z,feat
__device__ float4 g_pix4[Mm];      // x,y,z,|p|^2
__device__ int    g_nbr[Mm*GKk];
__device__ float  g_h0[Bq*Mm*Hh];
__device__ float  g_h1[Bq*Mm*Hh];
__device__ float  g_part[Bq*96*Hh];
__device__ volatile int g_sink;

// ---------------- dummy (harness pre-launches 2; 1 dummy puts k_samp at overall idx 5) ----------------
__global__ void k_dummy() {
    if (threadIdx.x > 1000) g_sink = 1;   // never true for blockDim=32
}

// ---------------- K0: precompute packed unit vectors ----------------
__global__ void k_pre(const float* __restrict__ xxx, const float* __restrict__ ptp) {
    int i = blockIdx.x * blockDim.x + threadIdx.x;
    if (i < Bq * Nn) {
        int b = i / Nn, n = i - b * Nn;
        float th = xxx[b * 3 * Nn + n];
        float ph = xxx[b * 3 * Nn + Nn + n];
        float ft = xxx[b * 3 * Nn + 2 * Nn + n];
        float st, ct, sp, cp;
        sincosf(th, &st, &ct);
        sincosf(ph, &sp, &cp);
        g_los4[i] = make_float4(st * cp, st * sp, ct, ft);
    }
    if (i < Mm) {
        float th = ptp[2 * i], ph = ptp[2 * i + 1];
        float st, ct, sp, cp;
        sincosf(th, &st, &ct);
        sincosf(ph, &sp, &cp);
        float x = st * cp, y = st * sp, z = ct;
        g_pix4[i] = make_float4(x, y, z, x * x + y * y + z * z);
    }
}

// ---------------- K1: kNN graph (top-8 by dot, self excluded) ----------------
struct Top8 { float v[8]; int id[8]; float vmin; };

__device__ __forceinline__ void t8_init(Top8& t) {
#pragma unroll
    for (int i = 0; i < 8; i++) { t.v[i] = -1e30f; t.id[i] = -1; }
    t.vmin = -1e30f;
}

__device__ __forceinline__ void t8_push(Top8& t, float s, int j) {
    if (s > t.vmin) {
        bool done = false;
#pragma unroll
        for (int i = 0; i < 8; i++) {
            if (!done && t.v[i] == t.vmin) { t.v[i] = s; t.id[i] = j; done = true; }
        }
        float m = t.v[0];
#pragma unroll
        for (int i = 1; i < 8; i++) m = fminf(m, t.v[i]);
        t.vmin = m;
    }
}

__device__ __forceinline__ void t8_merge(Top8& t, int lane, int* __restrict__ out) {
    for (int r = 0; r < 8; r++) {
        float lv = t.v[0]; int ls = 0;
#pragma unroll
        for (int i = 1; i < 8; i++) { if (t.v[i] > lv) { lv = t.v[i]; ls = i; } }
        float bv = lv; int bl = lane;
        for (int off = 16; off; off >>= 1) {
            float ov = __shfl_down_sync(0xffffffffu, bv, off);
            int   ol = __shfl_down_sync(0xffffffffu, bl, off);
            if (ov > bv) { bv = ov; bl = ol; }
        }
        bl = __shfl_sync(0xffffffffu, bl, 0);
        int wj = -1;
        if (lane == bl) {
#pragma unroll
            for (int i = 0; i < 8; i++) {
                if (i == ls) { wj = t.id[i]; t.v[i] = -1e30f; }
            }
        }
        wj = __shfl_sync(0xffffffffu, wj, bl);
        if (lane == 0) out[r] = wj;
    }
}

__global__ void k_knn() {
    __shared__ float4 sp[1024];
    int tid = threadIdx.x, lane = tid & 31, w = tid >> 5;
    int i0 = blockIdx.x * 16 + w * 2;
    int i1 = i0 + 1;
    float4 p0 = g_pix4[i0];
    float4 p1 = g_pix4[i1];
    Top8 t0, t1; t8_init(t0); t8_init(t1);
    for (int c0 = 0; c0 < Mm; c0 += 1024) {
        for (int t = tid; t < 1024; t += 256) sp[t] = g_pix4[c0 + t];
        __syncthreads();
        for (int l = lane; l < 1024; l += 32) {
            int j = c0 + l;
            float4 c = sp[l];
            float s0 = 2.f * (p0.x * c.x + p0.y * c.y + p0.z * c.z) - c.w;
            float s1 = 2.f * (p1.x * c.x + p1.y * c.y + p1.z * c.z) - c.w;
            if (j == i0) s0 = -1e30f;
            if (j == i1) s1 = -1e30f;
            t8_push(t0, s0, j);
            t8_push(t1, s1, j);
        }
        __syncthreads();
    }
    t8_merge(t0, lane, &g_nbr[i0 * 8]);
    t8_merge(t1, lane, &g_nbr[i1 * 8]);
}

// ---------------- K2: sparse sampler (single-scan 8-rung ladder) ----------------
__device__ __forceinline__ int wred(int v) {
#pragma unroll
    for (int off = 16; off; off >>= 1) v += __shfl_xor_sync(0xffffffffu, v, off);
    return v;
}

__global__ void k_samp(const float* __restrict__ aw1, const float* __restrict__ ab1,
                       const float* __restrict__ aw2, const float* __restrict__ ab2,
                       const float* __restrict__ pw,  const float* __restrict__ pb) {
    __shared__ float  cv[16][SCAP];         // 12KB
    __shared__ int    cid[16][SCAP];        // 12KB
    __shared__ float  swv[16][Kk];          // 4KB
    __shared__ int    swid[16][Kk];         // 4KB
    __shared__ float  spool[16];
    __shared__ float  sw1x[32], sw1d[32], sb1[32], sw2[32];
    __shared__ float  sab2v;

    int tid = threadIdx.x, lane = tid & 31, w = tid >> 5;
    int b  = blockIdx.x / 768;
    int m0 = (blockIdx.x % 768) * 16;
    int pA = 2 * w, pB = 2 * w + 1;
    float4 qa = g_pix4[m0 + pA];
    float4 qb = g_pix4[m0 + pB];
    const float4* __restrict__ los = g_los4 + b * Nn;

    if (tid < 32) {
        sw1x[tid] = aw1[tid];
        sw1d[tid] = aw1[32 + tid];
        sb1[tid]  = ab1[tid];
        sw2[tid]  = aw2[tid];
    }
    if (tid == 0) sab2v = ab2[0];
    __syncthreads();

    // density-aware base radius (theta ~ U[0,pi] -> rho ~ 1/sin(theta)); target ~96
    float sA = sqrtf(qa.x * qa.x + qa.y * qa.y);
    float sB = sqrtf(qb.x * qb.x + qb.y * qb.y);
    float rA = fmaxf(0.0859f, 0.4145f * sqrtf(sA));
    float rB = fmaxf(0.0859f, 0.4145f * sqrtf(sB));

    // 8-rung geometric radius ladder (ratio 1.19)
    const float RF0 = 0.594f, RF1 = 0.707f, RF2 = 0.840f, RF3 = 1.000f;
    const float RF4 = 1.190f, RF5 = 1.416f, RF6 = 1.685f, RF7 = 2.005f;

    float thrA = 0.f, thrB = 0.f;
    int cntA = 0, cntB = 0;
    bool doneA = false, doneB = false;

    for (int att = 0; att < 8 && !(doneA && doneB); att++) {
        float tA[8], tB[8];
        tA[0] = cosf(fminf(rA * RF0, 3.14159f)); tA[1] = cosf(fminf(rA * RF1, 3.14159f));
        tA[2] = cosf(fminf(rA * RF2, 3.14159f)); tA[3] = cosf(fminf(rA * RF3, 3.14159f));
        tA[4] = cosf(fminf(rA * RF4, 3.14159f)); tA[5] = cosf(fminf(rA * RF5, 3.14159f));
        tA[6] = cosf(fminf(rA * RF6, 3.14159f)); tA[7] = cosf(fminf(rA * RF7, 3.14159f));
        tB[0] = cosf(fminf(rB * RF0, 3.14159f)); tB[1] = cosf(fminf(rB * RF1, 3.14159f));
        tB[2] = cosf(fminf(rB * RF2, 3.14159f)); tB[3] = cosf(fminf(rB * RF3, 3.14159f));
        tB[4] = cosf(fminf(rB * RF4, 3.14159f)); tB[5] = cosf(fminf(rB * RF5, 3.14159f));
        tB[6] = cosf(fminf(rB * RF6, 3.14159f)); tB[7] = cosf(fminf(rB * RF7, 3.14159f));
        int ca[8] = {0,0,0,0,0,0,0,0}, cb[8] = {0,0,0,0,0,0,0,0};
#pragma unroll 2
        for (int n = lane; n < Nn; n += 32) {
            float4 l = los[n];
            float va = fminf(1.f, fmaxf(-1.f, fmaf(l.x, qa.x, fmaf(l.y, qa.y, l.z * qa.z))));
            float vb = fminf(1.f, fmaxf(-1.f, fmaf(l.x, qb.x, fmaf(l.y, qb.y, l.z * qb.z))));
#pragma unroll
            for (int i = 0; i < 8; i++) { ca[i] += (va > tA[i]); cb[i] += (vb > tB[i]); }
        }
#pragma unroll
        for (int i = 0; i < 8; i++) { ca[i] = wred(ca[i]); cb[i] = wred(cb[i]); }
        if (!doneA) {
            int best = -1, bestd = 1 << 30;
#pragma unroll
            for (int i = 0; i < 8; i++) {
                int c = ca[i];
                if (c >= Kk && c <= SCAP) {
                    int d = (c > 112) ? (c - 112) : (112 - c);
                    if (d < bestd) { bestd = d; best = i; }
                }
            }
            if (best >= 0) { thrA = tA[best]; cntA = ca[best]; doneA = true; }
            else {
                float sc = sqrtf(96.f / fmaxf((float)ca[3], 4.f));
                rA = fminf(rA * fminf(fmaxf(sc, 0.3f), 4.f), 3.14159f);
            }
        }
        if (!doneB) {
            int best = -1, bestd = 1 << 30;
#pragma unroll
            for (int i = 0; i < 8; i++) {
                int c = cb[i];
                if (c >= Kk && c <= SCAP) {
                    int d = (c > 112) ? (c - 112) : (112 - c);
                    if (d < bestd) { bestd = d; best = i; }
                }
            }
            if (best >= 0) { thrB = tB[best]; cntB = cb[best]; doneB = true; }
            else {
                float sc = sqrtf(96.f / fmaxf((float)cb[3], 4.f));
                rB = fminf(rB * fminf(fmaxf(sc, 0.3f), 4.f), 3.14159f);
            }
        }
    }

    // collection pass: positions via running base (no atomics)
    {
        int baseA = 0, baseB = 0;
        unsigned ltm = (1u << lane) - 1u;
        for (int n = lane; n < Nn; n += 32) {
            float4 l = los[n];
            float va = fminf(1.f, fmaxf(-1.f, fmaf(l.x, qa.x, fmaf(l.y, qa.y, l.z * qa.z))));
            float vb = fminf(1.f, fmaxf(-1.f, fmaf(l.x, qb.x, fmaf(l.y, qb.y, l.z * qb.z))));
            bool hA = va > thrA;
            bool hB = vb > thrB;
            unsigned mA = __ballot_sync(0xffffffffu, hA);
            unsigned mB = __ballot_sync(0xffffffffu, hB);
            if (hA) {
                int pos = baseA + __popc(mA & ltm);
                if (pos < SCAP) { cv[pA][pos] = va; cid[pA][pos] = n; }
            }
            if (hB) {
                int pos = baseB + __popc(mB & ltm);
                if (pos < SCAP) { cv[pB][pos] = vb; cid[pB][pos] = n; }
            }
            baseA += __popc(mA);
            baseB += __popc(mB);
        }
    }
    __syncwarp();

    // exact top-64 by rank-count (ties -> lowest index); slot = rank (deterministic)
#pragma unroll
    for (int s = 0; s < 2; s++) {
        int pix = (s == 0) ? pA : pB;
        int cnt = min((s == 0) ? cntA : cntB, SCAP);
        for (int t = lane; t < cnt; t += 32) {
            float v = cv[pix][t]; int id = cid[pix][t];
            int rank = 0;
            for (int j = 0; j < cnt; j++) {
                float vj = cv[pix][j];
                int idj = cid[pix][j];
                rank += (vj > v) || (vj == v && idj < id);
            }
            if (rank < Kk) { swv[pix][rank] = v; swid[pix][rank] = id; }
        }
    }
    __syncwarp();

    // attention MLP + softmax pool per pixel (warp-local, 2 logits per lane)
#pragma unroll
    for (int s = 0; s < 2; s++) {
        int pix = (s == 0) ? pA : pB;
        float v0 = swv[pix][lane], v1 = swv[pix][lane + 32];
        int   i0 = swid[pix][lane], i1 = swid[pix][lane + 32];
        float x0 = los[i0].w, x1 = los[i1].w;
        float d0 = acosf(v0), d1 = acosf(v1);
        float l0 = sab2v, l1 = sab2v;
#pragma unroll
        for (int j = 0; j < 32; j++) {
            float h0 = fmaf(x0, sw1x[j], fmaf(d0, sw1d[j], sb1[j]));
            float h1 = fmaf(x1, sw1x[j], fmaf(d1, sw1d[j], sb1[j]));
            l0 = fmaf(fmaxf(h0, 0.f), sw2[j], l0);
            l1 = fmaf(fmaxf(h1, 0.f), sw2[j], l1);
        }
        float mx = fmaxf(l0, l1);
#pragma unroll
        for (int off = 16; off; off >>= 1) mx = fmaxf(mx, __shfl_xor_sync(0xffffffffu, mx, off));
        float e0 = __expf(l0 - mx), e1 = __expf(l1 - mx);
        float sm = e0 + e1;
        float wx = e0 * x0 + e1 * x1;
#pragma unroll
        for (int off = 16; off; off >>= 1) {
            sm += __shfl_xor_sync(0xffffffffu, sm, off);
            wx += __shfl_xor_sync(0xffffffffu, wx, off);
        }
        if (lane == 0) spool[pix] = wx / sm;
    }
    __syncthreads();

    // projection: 16 pixels x 64 features
    for (int i = tid; i < 16 * 64; i += 256) {
        int pix = i >> 6, c = i & 63;
        g_h0[(b * Mm + m0 + pix) * 64 + c] = fmaxf(fmaf(spool[pix], pw[c], pb[c]), 0.f);
    }
}

// ---------------- K3: GNN layer, two K=64 phases, 4x4 reg tiling ----------------
// smem floats: sAT[64][65] @0, sW[64][64] @4160, sbias @8256, snbr(int)[512] @8320
#define GNN_SMEMF 8832
__global__ void k_gnn(const float* __restrict__ relw, const float* __restrict__ relb,
                      const float* __restrict__ rootw, int layer, int dir) {
    extern __shared__ float smbuf[];
    float* sAT   = smbuf;                 // [k][r], stride 65
    float* sW    = smbuf + 4160;          // [k][c], stride 64
    float* sbias = smbuf + 8256;
    int*   snbr  = (int*)(smbuf + 8320);

    const float* hin  = dir ? g_h1 : g_h0;
    float*       hout = dir ? g_h0 : g_h1;

    int tid = threadIdx.x;
    int row0 = blockIdx.x * 64;
    int b = row0 / Mm;
    int m0 = row0 - b * Mm;

    // phase A: W = rel, A = neighbor-sum aggregate
    for (int i = tid; i < 4096; i += 256) sW[i] = relw[layer * 4096 + i];
    if (tid < 64) sbias[tid] = relb[layer * 64 + tid];
    for (int i = tid; i < 512; i += 256) snbr[i] = g_nbr[m0 * 8 + i];
    __syncthreads();
    {
        int c = tid & 63, rq = tid >> 6;
        for (int rr = rq; rr < 64; rr += 4) {
            float a = 0.f;
#pragma unroll
            for (int j = 0; j < 8; j++) a += hin[(b * Mm + snbr[rr * 8 + j]) * 64 + c];
            sAT[c * 65 + rr] = a;
        }
    }
    __syncthreads();

    int tx = tid & 15, ty = tid >> 4;
    int r0 = ty * 4, c0 = tx * 4;
    float acc[4][4];
#pragma unroll
    for (int i = 0; i < 4; i++)
#pragma unroll
        for (int j = 0; j < 4; j++) acc[i][j] = sbias[c0 + j];

#pragma unroll 4
    for (int k = 0; k < 64; k++) {
        float a0 = sAT[k * 65 + r0];
        float a1 = sAT[k * 65 + r0 + 1];
        float a2 = sAT[k * 65 + r0 + 2];
        float a3 = sAT[k * 65 + r0 + 3];
        float4 wv = *(const float4*)&sW[k * 64 + c0];
        acc[0][0] = fmaf(a0, wv.x, acc[0][0]); acc[0][1] = fmaf(a0, wv.y, acc[0][1]);
        acc[0][2] = fmaf(a0, wv.z, acc[0][2]); acc[0][3] = fmaf(a0, wv.w, acc[0][3]);
        acc[1][0] = fmaf(a1, wv.x, acc[1][0]); acc[1][1] = fmaf(a1, wv.y, acc[1][1]);
        acc[1][2] = fmaf(a1, wv.z, acc[1][2]); acc[1][3] = fmaf(a1, wv.w, acc[1][3]);
        acc[2][0] = fmaf(a2, wv.x, acc[2][0]); acc[2][1] = fmaf(a2, wv.y, acc[2][1]);
        acc[2][2] = fmaf(a2, wv.z, acc[2][2]); acc[2][3] = fmaf(a2, wv.w, acc[2][3]);
        acc[3][0] = fmaf(a3, wv.x, acc[3][0]); acc[3][1] = fmaf(a3, wv.y, acc[3][1]);
        acc[3][2] = fmaf(a3, wv.z, acc[3][2]); acc[3][3] = fmaf(a3, wv.w, acc[3][3]);
    }
    __syncthreads();

    // phase B: W = root, A = h tile (transposed)
    for (int i = tid; i < 4096; i += 256) sW[i] = rootw[layer * 4096 + i];
    for (int i = tid; i < 4096; i += 256) {
        int r = i >> 6, k = i & 63;
        sAT[k * 65 + r] = hin[row0 * 64 + i];
    }
    __syncthreads();

#pragma unroll 4
    for (int k = 0; k < 64; k++) {
        float a0 = sAT[k * 65 + r0];
        float a1 = sAT[k * 65 + r0 + 1];
        float a2 = sAT[k * 65 + r0 + 2];
        float a3 = sAT[k * 65 + r0 + 3];
        float4 wv = *(const float4*)&sW[k * 64 + c0];
        acc[0][0] = fmaf(a0, wv.x, acc[0][0]); acc[0][1] = fmaf(a0, wv.y, acc[0][1]);
        acc[0][2] = fmaf(a0, wv.z, acc[0][2]); acc[0][3] = fmaf(a0, wv.w, acc[0][3]);
        acc[1][0] = fmaf(a1, wv.x, acc[1][0]); acc[1][1] = fmaf(a1, wv.y, acc[1][1]);
        acc[1][2] = fmaf(a1, wv.z, acc[1][2]); acc[1][3] = fmaf(a1, wv.w, acc[1][3]);
        acc[2][0] = fmaf(a2, wv.x, acc[2][0]); acc[2][1] = fmaf(a2, wv.y, acc[2][1]);
        acc[2][2] = fmaf(a2, wv.z, acc[2][2]); acc[2][3] = fmaf(a2, wv.w, acc[2][3]);
        acc[3][0] = fmaf(a3, wv.x, acc[3][0]); acc[3][1] = fmaf(a3, wv.y, acc[3][1]);
        acc[3][2] = fmaf(a3, wv.z, acc[3][2]); acc[3][3] = fmaf(a3, wv.w, acc[3][3]);
    }

#pragma unroll
    for (int i = 0; i < 4; i++) {
        float4 o;
        o.x = fmaxf(acc[i][0], 0.f);
        o.y = fmaxf(acc[i][1], 0.f);
        o.z = fmaxf(acc[i][2], 0.f);
        o.w = fmaxf(acc[i][3], 0.f);
        *(float4*)&hout[(row0 + r0 + i) * 64 + c0] = o;
    }
}

// ---------------- K4a: partial mean-pool reduction ----------------
__global__ void k_red() {
    __shared__ float part[128];
    int tid = threadIdx.x;
    int blk = blockIdx.x;
    int b = blk / 96, seg = blk % 96;
    int c = tid & 63, half = tid >> 6;
    float a = 0.f;
    int mbase = seg * 128;
    for (int i = half; i < 128; i += 2)
        a += g_h1[(b * Mm + mbase + i) * 64 + c];
    part[tid] = a;
    __syncthreads();
    if (tid < 64) g_part[(b * 96 + seg) * 64 + c] = part[tid] + part[tid + 64];
}

// ---------------- K4b: final reduce + output MLP ----------------
__global__ void k_out(const float* __restrict__ ow1, const float* __restrict__ ob1,
                      const float* __restrict__ ow2, const float* __restrict__ ob2,
                      float* __restrict__ out) {
    __shared__ float sgf[64], shid[64];
    int tid = threadIdx.x;
    int b = blockIdx.x;
    if (tid < 64) {
        float a = 0.f;
        for (int s = 0; s < 96; s++) a += g_part[(b * 96 + s) * 64 + tid];
        sgf[tid] = a * (1.f / (float)Mm);
    }
    __syncthreads();
    if (tid < 64) {
        float a = ob1[tid];
        for (int k = 0; k < 64; k++) a = fmaf(sgf[k], ow1[k * 64 + tid], a);
        shid[tid] = fmaxf(a, 0.f);
    }
    __syncthreads();
    if (tid < NCc) {
        float a = ob2[tid];
        for (int k = 0; k < 64; k++) a = fmaf(shid[k], ow2[k * NCc + tid], a);
        out[b * NCc + tid] = a;
    }
}

// ---------------- launch ----------------
extern "C" void kernel_launch(void* const* d_in, const int* in_sizes, int n_in,
                              void* d_out, int out_size) {
    const float* xxx  = (const float*)d_in[0];
    const float* ptp  = (const float*)d_in[1];
    const float* aw1  = (const float*)d_in[2];
    const float* ab1  = (const float*)d_in[3];
    const float* aw2  = (const float*)d_in[4];
    const float* ab2  = (const float*)d_in[5];
    const float* pw   = (const float*)d_in[6];
    const float* pb   = (const float*)d_in[7];
    const float* relw = (const float*)d_in[8];
    const float* relb = (const float*)d_in[9];
    const float* rootw= (const float*)d_in[10];
    const float* ow1  = (const float*)d_in[11];
    const float* ob1  = (const float*)d_in[12];
    const float* ow2  = (const float*)d_in[13];
    const float* ob2  = (const float*)d_in[14];
    float* out = (float*)d_out;

    (void)in_sizes; (void)n_in; (void)out_size;

    k_pre<<<48, 256>>>(xxx, ptp);          // my idx 0 (harness pre-launches 2 -> overall 2)
    k_knn<<<Mm / 16, 256>>>();             // my idx 1 -> overall 3
    k_dummy<<<1, 32>>>();                  // my idx 2 -> overall 4
    k_samp<<<Bq * 768, 256>>>(aw1, ab1, aw2, ab2, pw, pb);  // my idx 3 -> overall 5 <- ncu -s 5 -c 1

    const int SM3 = GNN_SMEMF * 4;
    cudaFuncSetAttribute(k_gnn, cudaFuncAttributeMaxDynamicSharedMemorySize, SM3);
    k_gnn<<<384, 256, SM3>>>(relw, relb, rootw, 0, 0); // g_h0 -> g_h1
    k_gnn<<<384, 256, SM3>>>(relw, relb, rootw, 1, 1); // g_h1 -> g_h0
    k_gnn<<<384, 256, SM3>>>(relw, relb, rootw, 2, 0); // g_h0 -> g_h1

    k_red<<<Bq * 96, 128>>>();
    k_out<<<Bq, 256>>>(ow1, ob1, ow2, ob2, out);
}

// round 11
// speedup vs baseline: 2.4461x; 2.4378x over previous
#include <cuda_runtime.h>
#include <math.h>

#define Bq 2
#define Nn 4096
#define Mm 12288
#define Kk 64
#define Hh 64
#define GKk 8
#define NCc 200
#define SCAP 192
#define KCAP 48

// ---------------- scratch (static device globals; no allocation) ----------------
__device__ float4 g_los4[Bq*Nn];   // x,y,z,feat
__device__ float4 g_pix4[Mm];      // x,y,z,|p|^2
__device__ int    g_nbr[Mm*GKk];
__device__ float  g_h0[Bq*Mm*Hh];
__device__ float  g_h1[Bq*Mm*Hh];
__device__ float  g_part[Bq*96*Hh];
__device__ volatile int g_sink;

// ---------------- dummy (harness pre-launches 2; 1 dummy puts k_samp at overall idx 5) ----------------
__global__ void k_dummy() {
    if (threadIdx.x > 1000) g_sink = 1;
}

// ---------------- K0: precompute packed unit vectors ----------------
__global__ void k_pre(const float* __restrict__ xxx, const float* __restrict__ ptp) {
    int i = blockIdx.x * blockDim.x + threadIdx.x;
    if (i < Bq * Nn) {
        int b = i / Nn, n = i - b * Nn;
        float th = xxx[b * 3 * Nn + n];
        float ph = xxx[b * 3 * Nn + Nn + n];
        float ft = xxx[b * 3 * Nn + 2 * Nn + n];
        float st, ct, sp, cp;
        sincosf(th, &st, &ct);
        sincosf(ph, &sp, &cp);
        g_los4[i] = make_float4(st * cp, st * sp, ct, ft);
    }
    if (i < Mm) {
        float th = ptp[2 * i], ph = ptp[2 * i + 1];
        float st, ct, sp, cp;
        sincosf(th, &st, &ct);
        sincosf(ph, &sp, &cp);
        float x = st * cp, y = st * sp, z = ct;
        g_pix4[i] = make_float4(x, y, z, x * x + y * y + z * z);
    }
}

// ---------------- K1: kNN graph (threshold-collect + exact rank top-8) ----------------
__global__ void k_knn() {
    __shared__ float4 sp[1024];            // 16KB staged tile
    __shared__ float  kv[16][KCAP];        // 3KB
    __shared__ int    kid[16][KCAP];       // 3KB

    int tid = threadIdx.x, lane = tid & 31, w = tid >> 5;
    int pA = 2 * w, pB = 2 * w + 1;
    int i0 = blockIdx.x * 16 + pA;
    int i1 = blockIdx.x * 16 + pB;
    float4 p0 = g_pix4[i0];
    float4 p1 = g_pix4[i1];
    unsigned ltm = (1u << lane) - 1u;

    // analytic radius for ~24 candidates: count = M r^2/(2 pi sin(th)); pole: M r/pi
    float snA = sqrtf(p0.x * p0.x + p0.y * p0.y);
    float snB = sqrtf(p1.x * p1.x + p1.y * p1.y);
    float rA = fmaxf(0.00614f, 0.1108f * sqrtf(snA));
    float rB = fmaxf(0.00614f, 0.1108f * sqrtf(snB));
    float thrA = 2.f * cosf(rA) - 1.f;     // score = 2*dot - |c|^2, |c|~1
    float thrB = 2.f * cosf(rB) - 1.f;

    // first pass: staged tiles, all warps collect
    int cntA, cntB;
    {
        int baseA = 0, baseB = 0;
        for (int c0 = 0; c0 < Mm; c0 += 1024) {
            for (int t = tid; t < 1024; t += 256) sp[t] = g_pix4[c0 + t];
            __syncthreads();
            for (int l = lane; l < 1024; l += 32) {
                int j = c0 + l;
                float4 cd = sp[l];
                float s0 = 2.f * fmaf(p0.x, cd.x, fmaf(p0.y, cd.y, p0.z * cd.z)) - cd.w;
                float s1 = 2.f * fmaf(p1.x, cd.x, fmaf(p1.y, cd.y, p1.z * cd.z)) - cd.w;
                bool hA = (s0 > thrA) && (j != i0);
                bool hB = (s1 > thrB) && (j != i1);
                unsigned mA = __ballot_sync(0xffffffffu, hA);
                unsigned mB = __ballot_sync(0xffffffffu, hB);
                if (hA) {
                    int pos = baseA + __popc(mA & ltm);
                    if (pos < KCAP) { kv[pA][pos] = s0; kid[pA][pos] = j; }
                }
                if (hB) {
                    int pos = baseB + __popc(mB & ltm);
                    if (pos < KCAP) { kv[pB][pos] = s1; kid[pB][pos] = j; }
                }
                baseA += __popc(mA);
                baseB += __popc(mB);
            }
            __syncthreads();
        }
        cntA = baseA; cntB = baseB;
    }
    bool needA = !(cntA >= GKk && cntA <= KCAP);
    bool needB = !(cntB >= GKk && cntB <= KCAP);
    if (needA) { rA = fminf(rA * sqrtf(24.f / fmaxf((float)cntA, 2.f)), 3.1416f); thrA = 2.f * cosf(rA) - 1.f; }
    if (needB) { rB = fminf(rB * sqrtf(24.f / fmaxf((float)cntB, 2.f)), 3.1416f); thrB = 2.f * cosf(rB) - 1.f; }

    // rare retries: warp-private, direct LDG (no block coupling)
    int att = 0;
    while ((needA || needB) && att < 20) {
        att++;
        int baseA = 0, baseB = 0;
        for (int j = lane; j < Mm; j += 32) {
            float4 cd = g_pix4[j];
            float s0 = 2.f * fmaf(p0.x, cd.x, fmaf(p0.y, cd.y, p0.z * cd.z)) - cd.w;
            float s1 = 2.f * fmaf(p1.x, cd.x, fmaf(p1.y, cd.y, p1.z * cd.z)) - cd.w;
            bool hA = needA && (s0 > thrA) && (j != i0);
            bool hB = needB && (s1 > thrB) && (j != i1);
            unsigned mA = __ballot_sync(0xffffffffu, hA);
            unsigned mB = __ballot_sync(0xffffffffu, hB);
            if (hA) {
                int pos = baseA + __popc(mA & ltm);
                if (pos < KCAP) { kv[pA][pos] = s0; kid[pA][pos] = j; }
            }
            if (hB) {
                int pos = baseB + __popc(mB & ltm);
                if (pos < KCAP) { kv[pB][pos] = s1; kid[pB][pos] = j; }
            }
            baseA += __popc(mA);
            baseB += __popc(mB);
        }
        if (needA) {
            cntA = baseA;
            if (cntA >= GKk && cntA <= KCAP) needA = false;
            else { rA = fminf(rA * sqrtf(24.f / fmaxf((float)cntA, 2.f)), 3.1416f); thrA = 2.f * cosf(rA) - 1.f; }
        }
        if (needB) {
            cntB = baseB;
            if (cntB >= GKk && cntB <= KCAP) needB = false;
            else { rB = fminf(rB * sqrtf(24.f / fmaxf((float)cntB, 2.f)), 3.1416f); thrB = 2.f * cosf(rB) - 1.f; }
        }
    }
    __syncwarp();

    // exact top-8 by rank-count (ties -> lowest index); write g_nbr by rank
#pragma unroll
    for (int s = 0; s < 2; s++) {
        int pix = (s == 0) ? pA : pB;
        int gpix = blockIdx.x * 16 + pix;
        int cnt = min((s == 0) ? cntA : cntB, KCAP);
        for (int t = lane; t < cnt; t += 32) {
            float v = kv[pix][t]; int id = kid[pix][t];
            int rank = 0;
            for (int j2 = 0; j2 < cnt; j2++) {
                float vj = kv[pix][j2];
                int idj = kid[pix][j2];
                rank += (vj > v) || (vj == v && idj < id);
            }
            if (rank < GKk) g_nbr[gpix * GKk + rank] = id;
        }
    }
}

// ---------------- K2: sparse sampler (single-scan threshold collect) ----------------
__global__ void k_samp(const float* __restrict__ aw1, const float* __restrict__ ab1,
                       const float* __restrict__ aw2, const float* __restrict__ ab2,
                       const float* __restrict__ pw,  const float* __restrict__ pb) {
    __shared__ float  cv[16][SCAP];         // 12KB
    __shared__ int    cid[16][SCAP];        // 12KB
    __shared__ float  swv[16][Kk];          // 4KB
    __shared__ int    swid[16][Kk];         // 4KB
    __shared__ float  spool[16];
    __shared__ float  sw1x[32], sw1d[32], sb1[32], sw2[32];
    __shared__ float  sab2v;

    int tid = threadIdx.x, lane = tid & 31, w = tid >> 5;
    int b  = blockIdx.x / 768;
    int m0 = (blockIdx.x % 768) * 16;
    int pA = 2 * w, pB = 2 * w + 1;
    float4 qa = g_pix4[m0 + pA];
    float4 qb = g_pix4[m0 + pB];
    const float4* __restrict__ los = g_los4 + b * Nn;
    unsigned ltm = (1u << lane) - 1u;

    if (tid < 32) {
        sw1x[tid] = aw1[tid];
        sw1d[tid] = aw1[32 + tid];
        sb1[tid]  = ab1[tid];
        sw2[tid]  = aw2[tid];
    }
    if (tid == 0) sab2v = ab2[0];
    __syncthreads();

    // analytic radius: target ~112 of 4096; pole regime r = 112*pi/4096
    float snA = sqrtf(qa.x * qa.x + qa.y * qa.y);
    float snB = sqrtf(qb.x * qb.x + qb.y * qb.y);
    float rA = fmaxf(0.0859f, 0.4145f * sqrtf(snA));
    float rB = fmaxf(0.0859f, 0.4145f * sqrtf(snB));
    float thrA = cosf(rA), thrB = cosf(rB);

    int cntA = 0, cntB = 0;
    bool needA = true, needB = true;
    int att = 0;
    while ((needA || needB) && att < 24) {
        att++;
        int baseA = 0, baseB = 0;
        for (int n = lane; n < Nn; n += 32) {
            float4 l = los[n];
            float va = fmaf(l.x, qa.x, fmaf(l.y, qa.y, l.z * qa.z));
            float vb = fmaf(l.x, qb.x, fmaf(l.y, qb.y, l.z * qb.z));
            va = fminf(1.f, fmaxf(-1.f, va));
            vb = fminf(1.f, fmaxf(-1.f, vb));
            bool hA = needA && (va > thrA);
            bool hB = needB && (vb > thrB);
            unsigned mA = __ballot_sync(0xffffffffu, hA);
            unsigned mB = __ballot_sync(0xffffffffu, hB);
            if (hA) {
                int pos = baseA + __popc(mA & ltm);
                if (pos < SCAP) { cv[pA][pos] = va; cid[pA][pos] = n; }
            }
            if (hB) {
                int pos = baseB + __popc(mB & ltm);
                if (pos < SCAP) { cv[pB][pos] = vb; cid[pB][pos] = n; }
            }
            baseA += __popc(mA);
            baseB += __popc(mB);
        }
        if (needA) {
            cntA = baseA;
            if (cntA >= Kk && cntA <= SCAP) needA = false;
            else { rA = fminf(rA * sqrtf(112.f / fmaxf((float)cntA, 2.f)), 3.1416f); thrA = cosf(rA); }
        }
        if (needB) {
            cntB = baseB;
            if (cntB >= Kk && cntB <= SCAP) needB = false;
            else { rB = fminf(rB * sqrtf(112.f / fmaxf((float)cntB, 2.f)), 3.1416f); thrB = cosf(rB); }
        }
    }
    __syncwarp();

    // exact top-64 by rank-count (ties -> lowest index); slot = rank (deterministic)
#pragma unroll
    for (int s = 0; s < 2; s++) {
        int pix = (s == 0) ? pA : pB;
        int cnt = min((s == 0) ? cntA : cntB, SCAP);
        for (int t = lane; t < cnt; t += 32) {
            float v = cv[pix][t]; int id = cid[pix][t];
            int rank = 0;
            for (int j = 0; j < cnt; j++) {
                float vj = cv[pix][j];
                int idj = cid[pix][j];
                rank += (vj > v) || (vj == v && idj < id);
            }
            if (rank < Kk) { swv[pix][rank] = v; swid[pix][rank] = id; }
        }
    }
    __syncwarp();

    // attention MLP + softmax pool per pixel (warp-local, 2 logits per lane)
#pragma unroll
    for (int s = 0; s < 2; s++) {
        int pix = (s == 0) ? pA : pB;
        float v0 = swv[pix][lane], v1 = swv[pix][lane + 32];
        int   i0 = swid[pix][lane], i1 = swid[pix][lane + 32];
        float x0 = los[i0].w, x1 = los[i1].w;
        float d0 = acosf(v0), d1 = acosf(v1);
        float l0 = sab2v, l1 = sab2v;
#pragma unroll
        for (int j = 0; j < 32; j++) {
            float h0 = fmaf(x0, sw1x[j], fmaf(d0, sw1d[j], sb1[j]));
            float h1 = fmaf(x1, sw1x[j], fmaf(d1, sw1d[j], sb1[j]));
            l0 = fmaf(fmaxf(h0, 0.f), sw2[j], l0);
            l1 = fmaf(fmaxf(h1, 0.f), sw2[j], l1);
        }
        float mx = fmaxf(l0, l1);
#pragma unroll
        for (int off = 16; off; off >>= 1) mx = fmaxf(mx, __shfl_xor_sync(0xffffffffu, mx, off));
        float e0 = __expf(l0 - mx), e1 = __expf(l1 - mx);
        float sm = e0 + e1;
        float wx = e0 * x0 + e1 * x1;
#pragma unroll
        for (int off = 16; off; off >>= 1) {
            sm += __shfl_xor_sync(0xffffffffu, sm, off);
            wx += __shfl_xor_sync(0xffffffffu, wx, off);
        }
        if (lane == 0) spool[pix] = wx / sm;
    }
    __syncthreads();

    // projection: 16 pixels x 64 features
    for (int i = tid; i < 16 * 64; i += 256) {
        int pix = i >> 6, c = i & 63;
        g_h0[(b * Mm + m0 + pix) * 64 + c] = fmaxf(fmaf(spool[pix], pw[c], pb[c]), 0.f);
    }
}

// ---------------- K3: GNN layer, two K=64 phases, 4x4 reg tiling ----------------
// smem floats: sAT[64][65] @0, sW[64][64] @4160, sbias @8256, snbr(int)[512] @8320
#define GNN_SMEMF 8832
__global__ void k_gnn(const float* __restrict__ relw, const float* __restrict__ relb,
                      const float* __restrict__ rootw, int layer, int dir) {
    extern __shared__ float smbuf[];
    float* sAT   = smbuf;                 // [k][r], stride 65
    float* sW    = smbuf + 4160;          // [k][c], stride 64
    float* sbias = smbuf + 8256;
    int*   snbr  = (int*)(smbuf + 8320);

    const float* hin  = dir ? g_h1 : g_h0;
    float*       hout = dir ? g_h0 : g_h1;

    int tid = threadIdx.x;
    int row0 = blockIdx.x * 64;
    int b = row0 / Mm;
    int m0 = row0 - b * Mm;

    // phase A: W = rel, A = neighbor-sum aggregate
    for (int i = tid; i < 4096; i += 256) sW[i] = relw[layer * 4096 + i];
    if (tid < 64) sbias[tid] = relb[layer * 64 + tid];
    for (int i = tid; i < 512; i += 256) snbr[i] = g_nbr[m0 * 8 + i];
    __syncthreads();
    {
        int c = tid & 63, rq = tid >> 6;
        for (int rr = rq; rr < 64; rr += 4) {
            float a = 0.f;
#pragma unroll
            for (int j = 0; j < 8; j++) a += hin[(b * Mm + snbr[rr * 8 + j]) * 64 + c];
            sAT[c * 65 + rr] = a;
        }
    }
    __syncthreads();

    int tx = tid & 15, ty = tid >> 4;
    int r0 = ty * 4, c0 = tx * 4;
    float acc[4][4];
#pragma unroll
    for (int i = 0; i < 4; i++)
#pragma unroll
        for (int j = 0; j < 4; j++) acc[i][j] = sbias[c0 + j];

#pragma unroll 4
    for (int k = 0; k < 64; k++) {
        float a0 = sAT[k * 65 + r0];
        float a1 = sAT[k * 65 + r0 + 1];
        float a2 = sAT[k * 65 + r0 + 2];
        float a3 = sAT[k * 65 + r0 + 3];
        float4 wv = *(const float4*)&sW[k * 64 + c0];
        acc[0][0] = fmaf(a0, wv.x, acc[0][0]); acc[0][1] = fmaf(a0, wv.y, acc[0][1]);
        acc[0][2] = fmaf(a0, wv.z, acc[0][2]); acc[0][3] = fmaf(a0, wv.w, acc[0][3]);
        acc[1][0] = fmaf(a1, wv.x, acc[1][0]); acc[1][1] = fmaf(a1, wv.y, acc[1][1]);
        acc[1][2] = fmaf(a1, wv.z, acc[1][2]); acc[1][3] = fmaf(a1, wv.w, acc[1][3]);
        acc[2][0] = fmaf(a2, wv.x, acc[2][0]); acc[2][1] = fmaf(a2, wv.y, acc[2][1]);
        acc[2][2] = fmaf(a2, wv.z, acc[2][2]); acc[2][3] = fmaf(a2, wv.w, acc[2][3]);
        acc[3][0] = fmaf(a3, wv.x, acc[3][0]); acc[3][1] = fmaf(a3, wv.y, acc[3][1]);
        acc[3][2] = fmaf(a3, wv.z, acc[3][2]); acc[3][3] = fmaf(a3, wv.w, acc[3][3]);
    }
    __syncthreads();

    // phase B: W = root, A = h tile (transposed)
    for (int i = tid; i < 4096; i += 256) sW[i] = rootw[layer * 4096 + i];
    for (int i = tid; i < 4096; i += 256) {
        int r = i >> 6, k = i & 63;
        sAT[k * 65 + r] = hin[row0 * 64 + i];
    }
    __syncthreads();

#pragma unroll 4
    for (int k = 0; k < 64; k++) {
        float a0 = sAT[k * 65 + r0];
        float a1 = sAT[k * 65 + r0 + 1];
        float a2 = sAT[k * 65 + r0 + 2];
        float a3 = sAT[k * 65 + r0 + 3];
        float4 wv = *(const float4*)&sW[k * 64 + c0];
        acc[0][0] = fmaf(a0, wv.x, acc[0][0]); acc[0][1] = fmaf(a0, wv.y, acc[0][1]);
        acc[0][2] = fmaf(a0, wv.z, acc[0][2]); acc[0][3] = fmaf(a0, wv.w, acc[0][3]);
        acc[1][0] = fmaf(a1, wv.x, acc[1][0]); acc[1][1] = fmaf(a1, wv.y, acc[1][1]);
        acc[1][2] = fmaf(a1, wv.z, acc[1][2]); acc[1][3] = fmaf(a1, wv.w, acc[1][3]);
        acc[2][0] = fmaf(a2, wv.x, acc[2][0]); acc[2][1] = fmaf(a2, wv.y, acc[2][1]);
        acc[2][2] = fmaf(a2, wv.z, acc[2][2]); acc[2][3] = fmaf(a2, wv.w, acc[2][3]);
        acc[3][0] = fmaf(a3, wv.x, acc[3][0]); acc[3][1] = fmaf(a3, wv.y, acc[3][1]);
        acc[3][2] = fmaf(a3, wv.z, acc[3][2]); acc[3][3] = fmaf(a3, wv.w, acc[3][3]);
    }

#pragma unroll
    for (int i = 0; i < 4; i++) {
        float4 o;
        o.x = fmaxf(acc[i][0], 0.f);
        o.y = fmaxf(acc[i][1], 0.f);
        o.z = fmaxf(acc[i][2], 0.f);
        o.w = fmaxf(acc[i][3], 0.f);
        *(float4*)&hout[(row0 + r0 + i) * 64 + c0] = o;
    }
}

// ---------------- K4a: partial mean-pool reduction ----------------
__global__ void k_red() {
    __shared__ float part[128];
    int tid = threadIdx.x;
    int blk = blockIdx.x;
    int b = blk / 96, seg = blk % 96;
    int c = tid & 63, half = tid >> 6;
    float a = 0.f;
    int mbase = seg * 128;
    for (int i = half; i < 128; i += 2)
        a += g_h1[(b * Mm + mbase + i) * 64 + c];
    part[tid] = a;
    __syncthreads();
    if (tid < 64) g_part[(b * 96 + seg) * 64 + c] = part[tid] + part[tid + 64];
}

// ---------------- K4b: final reduce + output MLP ----------------
__global__ void k_out(const float* __restrict__ ow1, const float* __restrict__ ob1,
                      const float* __restrict__ ow2, const float* __restrict__ ob2,
                      float* __restrict__ out) {
    __shared__ float sgf[64], shid[64];
    int tid = threadIdx.x;
    int b = blockIdx.x;
    if (tid < 64) {
        float a = 0.f;
        for (int s = 0; s < 96; s++) a += g_part[(b * 96 + s) * 64 + tid];
        sgf[tid] = a * (1.f / (float)Mm);
    }
    __syncthreads();
    if (tid < 64) {
        float a = ob1[tid];
        for (int k = 0; k < 64; k++) a = fmaf(sgf[k], ow1[k * 64 + tid], a);
        shid[tid] = fmaxf(a, 0.f);
    }
    __syncthreads();
    if (tid < NCc) {
        float a = ob2[tid];
        for (int k = 0; k < 64; k++) a = fmaf(shid[k], ow2[k * NCc + tid], a);
        out[b * NCc + tid] = a;
    }
}

// ---------------- launch ----------------
extern "C" void kernel_launch(void* const* d_in, const int* in_sizes, int n_in,
                              void* d_out, int out_size) {
    const float* xxx  = (const float*)d_in[0];
    const float* ptp  = (const float*)d_in[1];
    const float* aw1  = (const float*)d_in[2];
    const float* ab1  = (const float*)d_in[3];
    const float* aw2  = (const float*)d_in[4];
    const float* ab2  = (const float*)d_in[5];
    const float* pw   = (const float*)d_in[6];
    const float* pb   = (const float*)d_in[7];
    const float* relw = (const float*)d_in[8];
    const float* relb = (const float*)d_in[9];
    const float* rootw= (const float*)d_in[10];
    const float* ow1  = (const float*)d_in[11];
    const float* ob1  = (const float*)d_in[12];
    const float* ow2  = (const float*)d_in[13];
    const float* ob2  = (const float*)d_in[14];
    float* out = (float*)d_out;

    (void)in_sizes; (void)n_in; (void)out_size;

    k_pre<<<48, 256>>>(xxx, ptp);          // my idx 0 (harness pre-launches 2 -> overall 2)
    k_knn<<<Mm / 16, 256>>>();             // my idx 1 -> overall 3
    k_dummy<<<1, 32>>>();                  // my idx 2 -> overall 4
    k_samp<<<Bq * 768, 256>>>(aw1, ab1, aw2, ab2, pw, pb);  // my idx 3 -> overall 5 <- ncu -s 5 -c 1

    const int SM3 = GNN_SMEMF * 4;
    cudaFuncSetAttribute(k_gnn, cudaFuncAttributeMaxDynamicSharedMemorySize, SM3);
    k_gnn<<<384, 256, SM3>>>(relw, relb, rootw, 0, 0); // g_h0 -> g_h1
    k_gnn<<<384, 256, SM3>>>(relw, relb, rootw, 1, 1); // g_h1 -> g_h0
    k_gnn<<<384, 256, SM3>>>(relw, relb, rootw, 2, 0); // g_h0 -> g_h1

    k_red<<<Bq * 96, 128>>>();
    k_out<<<Bq, 256>>>(ow1, ob1, ow2, ob2, out);
}

// round 12
// speedup vs baseline: 3.0643x; 1.2528x over previous
#include <cuda_runtime.h>
#include <math.h>

#define Bq 2
#define Nn 4096
#define Mm 12288
#define Kk 64
#define Hh 64
#define GKk 8
#define NCc 200
#define SCAP 192
#define KCAP 48

// ---------------- scratch (static device globals; no allocation) ----------------
__device__ float4 g_los4[Bq*Nn];   // x,y,z,feat
__device__ float4 g_pix4[Mm];      // x,y,z,|p|^2
__device__ int    g_nbr[Mm*GKk];
__device__ float  g_h0[Bq*Mm*Hh];
__device__ float  g_h1[Bq*Mm*Hh];
__device__ float  g_part[Bq*96*Hh];
__device__ volatile int g_sink;

// ---------------- dummy (harness pre-launches 2; keeps k_samp at overall idx 5) ----------------
__global__ void k_dummy() {
    if (threadIdx.x > 1000) g_sink = 1;
}

// ---------------- K0: precompute packed unit vectors ----------------
__global__ void k_pre(const float* __restrict__ xxx, const float* __restrict__ ptp) {
    int i = blockIdx.x * blockDim.x + threadIdx.x;
    if (i < Bq * Nn) {
        int b = i / Nn, n = i - b * Nn;
        float th = xxx[b * 3 * Nn + n];
        float ph = xxx[b * 3 * Nn + Nn + n];
        float ft = xxx[b * 3 * Nn + 2 * Nn + n];
        float st, ct, sp, cp;
        sincosf(th, &st, &ct);
        sincosf(ph, &sp, &cp);
        g_los4[i] = make_float4(st * cp, st * sp, ct, ft);
    }
    if (i < Mm) {
        float th = ptp[2 * i], ph = ptp[2 * i + 1];
        float st, ct, sp, cp;
        sincosf(th, &st, &ct);
        sincosf(ph, &sp, &cp);
        float x = st * cp, y = st * sp, z = ct;
        g_pix4[i] = make_float4(x, y, z, x * x + y * y + z * z);
    }
}

// ---------------- K1: kNN graph (threshold-collect + exact rank top-8) ----------------
__global__ void k_knn() {
    __shared__ float4 sp[1024];            // 16KB staged tile
    __shared__ float  kv[16][KCAP];        // 3KB
    __shared__ int    kid[16][KCAP];       // 3KB

    int tid = threadIdx.x, lane = tid & 31, w = tid >> 5;
    int pA = 2 * w, pB = 2 * w + 1;
    int i0 = blockIdx.x * 16 + pA;
    int i1 = blockIdx.x * 16 + pB;
    float4 p0 = g_pix4[i0];
    float4 p1 = g_pix4[i1];
    unsigned ltm = (1u << lane) - 1u;

    float snA = sqrtf(p0.x * p0.x + p0.y * p0.y);
    float snB = sqrtf(p1.x * p1.x + p1.y * p1.y);
    float rA = fmaxf(0.00614f, 0.1108f * sqrtf(snA));
    float rB = fmaxf(0.00614f, 0.1108f * sqrtf(snB));
    float thrA = 2.f * cosf(rA) - 1.f;
    float thrB = 2.f * cosf(rB) - 1.f;

    int cntA, cntB;
    {
        int baseA = 0, baseB = 0;
        for (int c0 = 0; c0 < Mm; c0 += 1024) {
            for (int t = tid; t < 1024; t += 256) sp[t] = g_pix4[c0 + t];
            __syncthreads();
            for (int l = lane; l < 1024; l += 32) {
                int j = c0 + l;
                float4 cd = sp[l];
                float s0 = 2.f * fmaf(p0.x, cd.x, fmaf(p0.y, cd.y, p0.z * cd.z)) - cd.w;
                float s1 = 2.f * fmaf(p1.x, cd.x, fmaf(p1.y, cd.y, p1.z * cd.z)) - cd.w;
                bool hA = (s0 > thrA) && (j != i0);
                bool hB = (s1 > thrB) && (j != i1);
                unsigned mA = __ballot_sync(0xffffffffu, hA);
                unsigned mB = __ballot_sync(0xffffffffu, hB);
                if (hA) {
                    int pos = baseA + __popc(mA & ltm);
                    if (pos < KCAP) { kv[pA][pos] = s0; kid[pA][pos] = j; }
                }
                if (hB) {
                    int pos = baseB + __popc(mB & ltm);
                    if (pos < KCAP) { kv[pB][pos] = s1; kid[pB][pos] = j; }
                }
                baseA += __popc(mA);
                baseB += __popc(mB);
            }
            __syncthreads();
        }
        cntA = baseA; cntB = baseB;
    }
    bool needA = !(cntA >= GKk && cntA <= KCAP);
    bool needB = !(cntB >= GKk && cntB <= KCAP);
    if (needA) { rA = fminf(rA * sqrtf(24.f / fmaxf((float)cntA, 2.f)), 3.1416f); thrA = 2.f * cosf(rA) - 1.f; }
    if (needB) { rB = fminf(rB * sqrtf(24.f / fmaxf((float)cntB, 2.f)), 3.1416f); thrB = 2.f * cosf(rB) - 1.f; }

    int att = 0;
    while ((needA || needB) && att < 20) {
        att++;
        int baseA = 0, baseB = 0;
        for (int j = lane; j < Mm; j += 32) {
            float4 cd = g_pix4[j];
            float s0 = 2.f * fmaf(p0.x, cd.x, fmaf(p0.y, cd.y, p0.z * cd.z)) - cd.w;
            float s1 = 2.f * fmaf(p1.x, cd.x, fmaf(p1.y, cd.y, p1.z * cd.z)) - cd.w;
            bool hA = needA && (s0 > thrA) && (j != i0);
            bool hB = needB && (s1 > thrB) && (j != i1);
            unsigned mA = __ballot_sync(0xffffffffu, hA);
            unsigned mB = __ballot_sync(0xffffffffu, hB);
            if (hA) {
                int pos = baseA + __popc(mA & ltm);
                if (pos < KCAP) { kv[pA][pos] = s0; kid[pA][pos] = j; }
            }
            if (hB) {
                int pos = baseB + __popc(mB & ltm);
                if (pos < KCAP) { kv[pB][pos] = s1; kid[pB][pos] = j; }
            }
            baseA += __popc(mA);
            baseB += __popc(mB);
        }
        if (needA) {
            cntA = baseA;
            if (cntA >= GKk && cntA <= KCAP) needA = false;
            else { rA = fminf(rA * sqrtf(24.f / fmaxf((float)cntA, 2.f)), 3.1416f); thrA = 2.f * cosf(rA) - 1.f; }
        }
        if (needB) {
            cntB = baseB;
            if (cntB >= GKk && cntB <= KCAP) needB = false;
            else { rB = fminf(rB * sqrtf(24.f / fmaxf((float)cntB, 2.f)), 3.1416f); thrB = 2.f * cosf(rB) - 1.f; }
        }
    }
    __syncwarp();

#pragma unroll
    for (int s = 0; s < 2; s++) {
        int pix = (s == 0) ? pA : pB;
        int gpix = blockIdx.x * 16 + pix;
        int cnt = min((s == 0) ? cntA : cntB, KCAP);
        for (int t = lane; t < cnt; t += 32) {
            float v = kv[pix][t]; int id = kid[pix][t];
            int rank = 0;
            for (int j2 = 0; j2 < cnt; j2++) {
                float vj = kv[pix][j2];
                int idj = kid[pix][j2];
                rank += (vj > v) || (vj == v && idj < id);
            }
            if (rank < GKk) g_nbr[gpix * GKk + rank] = id;
        }
    }
}

// ---------------- K2: sparse sampler (single-scan threshold collect) ----------------
__global__ void __launch_bounds__(256, 2)
k_samp(const float* __restrict__ aw1, const float* __restrict__ ab1,
       const float* __restrict__ aw2, const float* __restrict__ ab2,
       const float* __restrict__ pw,  const float* __restrict__ pb) {
    __shared__ float  cv[16][SCAP];         // 12KB
    __shared__ int    cid[16][SCAP];        // 12KB
    __shared__ float  swv[16][Kk];          // 4KB
    __shared__ int    swid[16][Kk];         // 4KB
    __shared__ float  spool[16];
    __shared__ float  sw1x[32], sw1d[32], sb1[32], sw2[32];
    __shared__ float  sab2v;

    int tid = threadIdx.x, lane = tid & 31, w = tid >> 5;
    int b  = blockIdx.x / 768;
    int m0 = (blockIdx.x % 768) * 16;
    int pA = 2 * w, pB = 2 * w + 1;
    float4 qa = g_pix4[m0 + pA];
    float4 qb = g_pix4[m0 + pB];
    const float4* __restrict__ los = g_los4 + b * Nn;
    unsigned ltm = (1u << lane) - 1u;

    if (tid < 32) {
        sw1x[tid] = aw1[tid];
        sw1d[tid] = aw1[32 + tid];
        sb1[tid]  = ab1[tid];
        sw2[tid]  = aw2[tid];
    }
    if (tid == 0) sab2v = ab2[0];
    __syncthreads();

    // analytic radius: target ~112 of 4096 (theta ~ U[0,pi] density)
    float snA = sqrtf(qa.x * qa.x + qa.y * qa.y);
    float snB = sqrtf(qb.x * qb.x + qb.y * qb.y);
    float rA = fmaxf(0.0859f, 0.4145f * sqrtf(snA));
    float rB = fmaxf(0.0859f, 0.4145f * sqrtf(snB));
    float thrA = cosf(rA), thrB = cosf(rB);   // thr <= 0.9963 < 1: unclamped compare == clamped compare

    int cntA = 0, cntB = 0;
    bool needA = true, needB = true;
    int att = 0;
    while ((needA || needB) && att < 24) {
        att++;
        int baseA = 0, baseB = 0;
        for (int n = lane; n < Nn; n += 32) {
            float4 l = los[n];
            float va = fmaf(l.x, qa.x, fmaf(l.y, qa.y, l.z * qa.z));
            float vb = fmaf(l.x, qb.x, fmaf(l.y, qb.y, l.z * qb.z));
            bool hA = needA && (va > thrA);
            bool hB = needB && (vb > thrB);
            unsigned mA = __ballot_sync(0xffffffffu, hA);
            unsigned mB = __ballot_sync(0xffffffffu, hB);
            if (hA) {
                int pos = baseA + __popc(mA & ltm);
                if (pos < SCAP) { cv[pA][pos] = va; cid[pA][pos] = n; }
            }
            if (hB) {
                int pos = baseB + __popc(mB & ltm);
                if (pos < SCAP) { cv[pB][pos] = vb; cid[pB][pos] = n; }
            }
            baseA += __popc(mA);
            baseB += __popc(mB);
        }
        if (needA) {
            cntA = baseA;
            if (cntA >= Kk && cntA <= SCAP) needA = false;
            else { rA = fminf(rA * sqrtf(112.f / fmaxf((float)cntA, 2.f)), 3.1416f); thrA = cosf(rA); }
        }
        if (needB) {
            cntB = baseB;
            if (cntB >= Kk && cntB <= SCAP) needB = false;
            else { rB = fminf(rB * sqrtf(112.f / fmaxf((float)cntB, 2.f)), 3.1416f); thrB = cosf(rB); }
        }
    }
    __syncwarp();

    // exact top-64 by rank-count (ties -> lowest index); slot = rank (deterministic)
#pragma unroll
    for (int s = 0; s < 2; s++) {
        int pix = (s == 0) ? pA : pB;
        int cnt = min((s == 0) ? cntA : cntB, SCAP);
        for (int t = lane; t < cnt; t += 32) {
            float v = cv[pix][t]; int id = cid[pix][t];
            int rank = 0;
            for (int j = 0; j < cnt; j++) {
                float vj = cv[pix][j];
                int idj = cid[pix][j];
                rank += (vj > v) || (vj == v && idj < id);
            }
            if (rank < Kk) { swv[pix][rank] = v; swid[pix][rank] = id; }
        }
    }
    __syncwarp();

    // attention MLP + softmax pool per pixel (warp-local, 2 logits per lane)
#pragma unroll
    for (int s = 0; s < 2; s++) {
        int pix = (s == 0) ? pA : pB;
        float v0 = swv[pix][lane], v1 = swv[pix][lane + 32];
        int   i0 = swid[pix][lane], i1 = swid[pix][lane + 32];
        float x0 = los[i0].w, x1 = los[i1].w;
        float d0 = acosf(fminf(1.f, fmaxf(-1.f, v0)));
        float d1 = acosf(fminf(1.f, fmaxf(-1.f, v1)));
        float l0 = sab2v, l1 = sab2v;
#pragma unroll
        for (int j = 0; j < 32; j++) {
            float h0 = fmaf(x0, sw1x[j], fmaf(d0, sw1d[j], sb1[j]));
            float h1 = fmaf(x1, sw1x[j], fmaf(d1, sw1d[j], sb1[j]));
            l0 = fmaf(fmaxf(h0, 0.f), sw2[j], l0);
            l1 = fmaf(fmaxf(h1, 0.f), sw2[j], l1);
        }
        float mx = fmaxf(l0, l1);
#pragma unroll
        for (int off = 16; off; off >>= 1) mx = fmaxf(mx, __shfl_xor_sync(0xffffffffu, mx, off));
        float e0 = __expf(l0 - mx), e1 = __expf(l1 - mx);
        float sm = e0 + e1;
        float wx = e0 * x0 + e1 * x1;
#pragma unroll
        for (int off = 16; off; off >>= 1) {
            sm += __shfl_xor_sync(0xffffffffu, sm, off);
            wx += __shfl_xor_sync(0xffffffffu, wx, off);
        }
        if (lane == 0) spool[pix] = wx / sm;
    }
    __syncthreads();

    // projection: 16 pixels x 64 features
    for (int i = tid; i < 16 * 64; i += 256) {
        int pix = i >> 6, c = i & 63;
        g_h0[(b * Mm + m0 + pix) * 64 + c] = fmaxf(fmaf(spool[pix], pw[c], pb[c]), 0.f);
    }
}

// ---------------- K3: GNN layer, 32-row tiles (768 blocks), two K=64 phases ----------------
// smem floats: sAT[64][33] @0 (2112), sW[64][64] @2112 (4096), sbias @6208, snbr(int)[256] @6272
#define GNN_SMEMF 6528
__global__ void k_gnn(const float* __restrict__ relw, const float* __restrict__ relb,
                      const float* __restrict__ rootw, int layer, int dir) {
    extern __shared__ float smbuf[];
    float* sAT   = smbuf;                 // [k][r], stride 33 (r < 32)
    float* sW    = smbuf + 2112;          // [k][c], stride 64
    float* sbias = smbuf + 6208;
    int*   snbr  = (int*)(smbuf + 6272);

    const float* hin  = dir ? g_h1 : g_h0;
    float*       hout = dir ? g_h0 : g_h1;

    int tid = threadIdx.x;
    int row0 = blockIdx.x * 32;
    int b = row0 / Mm;
    int m0 = row0 - b * Mm;

    // phase A: W = rel, A = neighbor-sum aggregate (32 rows)
    for (int i = tid; i < 4096; i += 256) sW[i] = relw[layer * 4096 + i];
    if (tid < 64) sbias[tid] = relb[layer * 64 + tid];
    if (tid < 256) snbr[tid] = g_nbr[m0 * 8 + tid];
    __syncthreads();
    {
        int c = tid & 63, rq = tid >> 6;
        for (int rr = rq; rr < 32; rr += 4) {
            float a = 0.f;
#pragma unroll
            for (int j = 0; j < 8; j++) a += hin[(b * Mm + snbr[rr * 8 + j]) * 64 + c];
            sAT[c * 33 + rr] = a;
        }
    }
    __syncthreads();

    int tx = tid & 15, ty = tid >> 4;
    int r0 = ty * 2, c0 = tx * 4;
    float acc[2][4];
#pragma unroll
    for (int i = 0; i < 2; i++)
#pragma unroll
        for (int j = 0; j < 4; j++) acc[i][j] = sbias[c0 + j];

#pragma unroll 4
    for (int k = 0; k < 64; k++) {
        float a0 = sAT[k * 33 + r0];
        float a1 = sAT[k * 33 + r0 + 1];
        float4 wv = *(const float4*)&sW[k * 64 + c0];
        acc[0][0] = fmaf(a0, wv.x, acc[0][0]); acc[0][1] = fmaf(a0, wv.y, acc[0][1]);
        acc[0][2] = fmaf(a0, wv.z, acc[0][2]); acc[0][3] = fmaf(a0, wv.w, acc[0][3]);
        acc[1][0] = fmaf(a1, wv.x, acc[1][0]); acc[1][1] = fmaf(a1, wv.y, acc[1][1]);
        acc[1][2] = fmaf(a1, wv.z, acc[1][2]); acc[1][3] = fmaf(a1, wv.w, acc[1][3]);
    }
    __syncthreads();

    // phase B: W = root, A = h tile (transposed)
    for (int i = tid; i < 4096; i += 256) sW[i] = rootw[layer * 4096 + i];
    for (int i = tid; i < 2048; i += 256) {
        int r = i >> 6, k = i & 63;
        sAT[k * 33 + r] = hin[row0 * 64 + i];
    }
    __syncthreads();

#pragma unroll 4
    for (int k = 0; k < 64; k++) {
        float a0 = sAT[k * 33 + r0];
        float a1 = sAT[k * 33 + r0 + 1];
        float4 wv = *(const float4*)&sW[k * 64 + c0];
        acc[0][0] = fmaf(a0, wv.x, acc[0][0]); acc[0][1] = fmaf(a0, wv.y, acc[0][1]);
        acc[0][2] = fmaf(a0, wv.z, acc[0][2]); acc[0][3] = fmaf(a0, wv.w, acc[0][3]);
        acc[1][0] = fmaf(a1, wv.x, acc[1][0]); acc[1][1] = fmaf(a1, wv.y, acc[1][1]);
        acc[1][2] = fmaf(a1, wv.z, acc[1][2]); acc[1][3] = fmaf(a1, wv.w, acc[1][3]);
    }

#pragma unroll
    for (int i = 0; i < 2; i++) {
        float4 o;
        o.x = fmaxf(acc[i][0], 0.f);
        o.y = fmaxf(acc[i][1], 0.f);
        o.z = fmaxf(acc[i][2], 0.f);
        o.w = fmaxf(acc[i][3], 0.f);
        *(float4*)&hout[(row0 + r0 + i) * 64 + c0] = o;
    }
}

// ---------------- K4a: partial mean-pool reduction ----------------
__global__ void k_red() {
    __shared__ float part[128];
    int tid = threadIdx.x;
    int blk = blockIdx.x;
    int b = blk / 96, seg = blk % 96;
    int c = tid & 63, half = tid >> 6;
    float a = 0.f;
    int mbase = seg * 128;
    for (int i = half; i < 128; i += 2)
        a += g_h1[(b * Mm + mbase + i) * 64 + c];
    part[tid] = a;
    __syncthreads();
    if (tid < 64) g_part[(b * 96 + seg) * 64 + c] = part[tid] + part[tid + 64];
}

// ---------------- K4b: final reduce + output MLP ----------------
__global__ void k_out(const float* __restrict__ ow1, const float* __restrict__ ob1,
                      const float* __restrict__ ow2, const float* __restrict__ ob2,
                      float* __restrict__ out) {
    __shared__ float sgf[64], shid[64];
    int tid = threadIdx.x;
    int b = blockIdx.x;
    if (tid < 64) {
        float a = 0.f;
        for (int s = 0; s < 96; s++) a += g_part[(b * 96 + s) * 64 + tid];
        sgf[tid] = a * (1.f / (float)Mm);
    }
    __syncthreads();
    if (tid < 64) {
        float a = ob1[tid];
        for (int k = 0; k < 64; k++) a = fmaf(sgf[k], ow1[k * 64 + tid], a);
        shid[tid] = fmaxf(a, 0.f);
    }
    __syncthreads();
    if (tid < NCc) {
        float a = ob2[tid];
        for (int k = 0; k < 64; k++) a = fmaf(shid[k], ow2[k * NCc + tid], a);
        out[b * NCc + tid] = a;
    }
}

// ---------------- launch ----------------
extern "C" void kernel_launch(void* const* d_in, const int* in_sizes, int n_in,
                              void* d_out, int out_size) {
    const float* xxx  = (const float*)d_in[0];
    const float* ptp  = (const float*)d_in[1];
    const float* aw1  = (const float*)d_in[2];
    const float* ab1  = (const float*)d_in[3];
    const float* aw2  = (const float*)d_in[4];
    const float* ab2  = (const float*)d_in[5];
    const float* pw   = (const float*)d_in[6];
    const float* pb   = (const float*)d_in[7];
    const float* relw = (const float*)d_in[8];
    const float* relb = (const float*)d_in[9];
    const float* rootw= (const float*)d_in[10];
    const float* ow1  = (const float*)d_in[11];
    const float* ob1  = (const float*)d_in[12];
    const float* ow2  = (const float*)d_in[13];
    const float* ob2  = (const float*)d_in[14];
    float* out = (float*)d_out;

    (void)in_sizes; (void)n_in; (void)out_size;

    k_pre<<<48, 256>>>(xxx, ptp);          // my idx 0 (harness pre-launches 2 -> overall 2)
    k_knn<<<Mm / 16, 256>>>();             // my idx 1 -> overall 3
    k_dummy<<<1, 32>>>();                  // my idx 2 -> overall 4
    k_samp<<<Bq * 768, 256>>>(aw1, ab1, aw2, ab2, pw, pb);  // my idx 3 -> overall 5 <- ncu -s 5 -c 1

    const int SM3 = GNN_SMEMF * 4;
    cudaFuncSetAttribute(k_gnn, cudaFuncAttributeMaxDynamicSharedMemorySize, SM3);
    k_gnn<<<768, 256, SM3>>>(relw, relb, rootw, 0, 0); // g_h0 -> g_h1
    k_gnn<<<768, 256, SM3>>>(relw, relb, rootw, 1, 1); // g_h1 -> g_h0
    k_gnn<<<768, 256, SM3>>>(relw, relb, rootw, 2, 0); // g_h0 -> g_h1

    k_red<<<Bq * 96, 128>>>();
    k_out<<<Bq, 256>>>(ow1, ob1, ow2, ob2, out);
}

// round 14
// speedup vs baseline: 3.8305x; 1.2500x over previous
#include <cuda_runtime.h>
#include <math.h>

#define Bq 2
#define Nn 4096
#define Mm 12288
#define Kk 64
#define Hh 64
#define GKk 8
#define NCc 200
#define SCAP 192
#define KCAP 48
#define NBAND 64
#define IBW (NBAND / 3.14159265f)

// ---------------- scratch (static device globals; no allocation) ----------------
__device__ float4 g_los4[Bq*Nn];    // x,y,z,feat (original order)
__device__ float4 g_pix4[Mm];       // x,y,z,|p|^2 (original order)
__device__ float4 g_los4s[Bq*Nn];   // theta-banded: x,y,z,origidx
__device__ float4 g_pix4s[Mm];      // theta-banded: x,y,z,origidx
__device__ int    g_loff[Bq*(NBAND+1)];
__device__ int    g_poff[NBAND+1];
__device__ int    g_nbr[Mm*GKk];
__device__ float  g_h0[Bq*Mm*Hh];
__device__ float  g_h1[Bq*Mm*Hh];
__device__ float  g_part[Bq*96*Hh];

// ---------------- K0: precompute packed unit vectors ----------------
__global__ void k_pre(const float* __restrict__ xxx, const float* __restrict__ ptp) {
    int i = blockIdx.x * blockDim.x + threadIdx.x;
    if (i < Bq * Nn) {
        int b = i / Nn, n = i - b * Nn;
        float th = xxx[b * 3 * Nn + n];
        float ph = xxx[b * 3 * Nn + Nn + n];
        float ft = xxx[b * 3 * Nn + 2 * Nn + n];
        float st, ct, sp, cp;
        sincosf(th, &st, &ct);
        sincosf(ph, &sp, &cp);
        g_los4[i] = make_float4(st * cp, st * sp, ct, ft);
    }
    if (i < Mm) {
        float th = ptp[2 * i], ph = ptp[2 * i + 1];
        float st, ct, sp, cp;
        sincosf(th, &st, &ct);
        sincosf(ph, &sp, &cp);
        float x = st * cp, y = st * sp, z = ct;
        g_pix4[i] = make_float4(x, y, z, x * x + y * y + z * z);
    }
}

// ---------------- K0b: theta-band counting sort (los per batch + pixels) ----------------
__global__ void k_sort(const float* __restrict__ xxx, const float* __restrict__ ptp) {
    __shared__ int hist[NBAND], woff[NBAND];
    int tid = threadIdx.x;
    int blk = blockIdx.x;           // 0,1: los batch; 2: pixels
    if (tid < NBAND) hist[tid] = 0;
    __syncthreads();
    if (blk < Bq) {
        int b = blk;
        const float* th = xxx + b * 3 * Nn;
        for (int i = tid; i < Nn; i += 256) {
            int band = min(NBAND - 1, max(0, (int)(th[i] * IBW)));
            atomicAdd(&hist[band], 1);
        }
        __syncthreads();
        if (tid == 0) {
            int s = 0;
            for (int k = 0; k < NBAND; k++) {
                woff[k] = s;
                g_loff[b * (NBAND + 1) + k] = s;
                s += hist[k];
            }
            g_loff[b * (NBAND + 1) + NBAND] = s;
        }
        __syncthreads();
        for (int i = tid; i < Nn; i += 256) {
            int band = min(NBAND - 1, max(0, (int)(th[i] * IBW)));
            int slot = atomicAdd(&woff[band], 1);
            float4 l = g_los4[b * Nn + i];
            g_los4s[b * Nn + slot] = make_float4(l.x, l.y, l.z, __int_as_float(i));
        }
    } else {
        for (int i = tid; i < Mm; i += 256) {
            int band = min(NBAND - 1, max(0, (int)(ptp[2 * i] * IBW)));
            atomicAdd(&hist[band], 1);
        }
        __syncthreads();
        if (tid == 0) {
            int s = 0;
            for (int k = 0; k < NBAND; k++) {
                woff[k] = s;
                g_poff[k] = s;
                s += hist[k];
            }
            g_poff[NBAND] = s;
        }
        __syncthreads();
        for (int i = tid; i < Mm; i += 256) {
            int band = min(NBAND - 1, max(0, (int)(ptp[2 * i] * IBW)));
            int slot = atomicAdd(&woff[band], 1);
            float4 p = g_pix4[i];
            g_pix4s[slot] = make_float4(p.x, p.y, p.z, __int_as_float(i));
        }
    }
}

// ---------------- K1: kNN graph (banded threshold-collect + exact rank top-8) ----------------
__global__ void __launch_bounds__(256, 2)
k_knn(const float* __restrict__ ptp) {
    __shared__ float kv[16][KCAP];
    __shared__ int   kid[16][KCAP];

    int tid = threadIdx.x, lane = tid & 31, w = tid >> 5;
    unsigned ltm = (1u << lane) - 1u;
    int cnts[2];

#pragma unroll
    for (int s = 0; s < 2; s++) {
        int pix = 2 * w + s;
        int gi = blockIdx.x * 16 + pix;
        float4 p = g_pix4[gi];
        float th = ptp[2 * gi];
        float sn = sqrtf(p.x * p.x + p.y * p.y);
        float r = fmaxf(0.00614f, 0.1108f * sqrtf(sn));
        float thr = 2.f * cosf(r) - 1.f;
        int cnt = 0;
        for (int att = 0; att < 24; att++) {
            int lo = max(0, (int)((th - r) * IBW) - 1);
            int hi = min(NBAND - 1, (int)((th + r) * IBW) + 1);
            int n0 = g_poff[lo], n1 = g_poff[hi + 1];
            int base = 0;
            // uniform trip count: every lane executes every ballot
            for (int nb = n0; nb < n1; nb += 32) {
                int n = nb + lane;
                bool valid = n < n1;
                float4 cd = g_pix4s[valid ? n : (n1 - 1)];
                float cq = fmaf(cd.x, cd.x, fmaf(cd.y, cd.y, cd.z * cd.z));
                int oid = __float_as_int(cd.w);
                float sc = 2.f * fmaf(p.x, cd.x, fmaf(p.y, cd.y, p.z * cd.z)) - cq;
                bool h = valid && (sc > thr) && (oid != gi);
                unsigned mk = __ballot_sync(0xffffffffu, h);
                if (h) {
                    int pos = base + __popc(mk & ltm);
                    if (pos < KCAP) { kv[pix][pos] = sc; kid[pix][pos] = oid; }
                }
                base += __popc(mk);
            }
            cnt = base;
            if (cnt >= GKk && cnt <= KCAP) break;
            r = fminf(r * sqrtf(24.f / fmaxf((float)cnt, 2.f)), 3.1416f);
            thr = 2.f * cosf(r) - 1.f;
        }
        cnts[s] = cnt;
    }
    __syncwarp();

#pragma unroll
    for (int s = 0; s < 2; s++) {
        int pix = 2 * w + s;
        int gpix = blockIdx.x * 16 + pix;
        int cnt = min(cnts[s], KCAP);
        for (int t = lane; t < cnt; t += 32) {
            float v = kv[pix][t]; int id = kid[pix][t];
            int rank = 0;
            for (int j2 = 0; j2 < cnt; j2++) {
                float vj = kv[pix][j2];
                int idj = kid[pix][j2];
                rank += (vj > v) || (vj == v && idj < id);
            }
            if (rank < GKk) g_nbr[gpix * GKk + rank] = id;
        }
    }
}

// ---------------- K2: sparse sampler (banded single-scan threshold collect) ----------------
__global__ void __launch_bounds__(256, 2)
k_samp(const float* __restrict__ ptp,
       const float* __restrict__ aw1, const float* __restrict__ ab1,
       const float* __restrict__ aw2, const float* __restrict__ ab2,
       const float* __restrict__ pw,  const float* __restrict__ pb) {
    __shared__ float  cv[16][SCAP];
    __shared__ int    cid[16][SCAP];
    __shared__ float  swv[16][Kk];
    __shared__ int    swid[16][Kk];
    __shared__ float  spool[16];
    __shared__ float  sw1x[32], sw1d[32], sb1[32], sw2[32];
    __shared__ float  sab2v;

    int tid = threadIdx.x, lane = tid & 31, w = tid >> 5;
    int b  = blockIdx.x / 768;
    int m0 = (blockIdx.x % 768) * 16;
    const float4* __restrict__ loss = g_los4s + b * Nn;
    const int* __restrict__ loff = g_loff + b * (NBAND + 1);
    unsigned ltm = (1u << lane) - 1u;

    if (tid < 32) {
        sw1x[tid] = aw1[tid];
        sw1d[tid] = aw1[32 + tid];
        sb1[tid]  = ab1[tid];
        sw2[tid]  = aw2[tid];
    }
    if (tid == 0) sab2v = ab2[0];
    __syncthreads();

    int cnts[2];
#pragma unroll
    for (int s = 0; s < 2; s++) {
        int pix = 2 * w + s;
        int gm = m0 + pix;
        float4 q = g_pix4[gm];
        float th = ptp[2 * gm];
        float sn = sqrtf(q.x * q.x + q.y * q.y);
        float r = fmaxf(0.0859f, 0.4145f * sqrtf(sn));
        float thr = cosf(r);
        int cnt = 0;
        for (int att = 0; att < 24; att++) {
            int lo = max(0, (int)((th - r) * IBW) - 1);
            int hi = min(NBAND - 1, (int)((th + r) * IBW) + 1);
            int n0 = loff[lo], n1 = loff[hi + 1];
            int base = 0;
            // uniform trip count: every lane executes every ballot
            for (int nb = n0; nb < n1; nb += 32) {
                int n = nb + lane;
                bool valid = n < n1;
                float4 l = loss[valid ? n : (n1 - 1)];
                float v = fmaf(l.x, q.x, fmaf(l.y, q.y, l.z * q.z));
                bool h = valid && (v > thr);
                unsigned mk = __ballot_sync(0xffffffffu, h);
                if (h) {
                    int pos = base + __popc(mk & ltm);
                    if (pos < SCAP) { cv[pix][pos] = v; cid[pix][pos] = __float_as_int(l.w); }
                }
                base += __popc(mk);
            }
            cnt = base;
            if (cnt >= Kk && cnt <= SCAP) break;
            r = fminf(r * sqrtf(112.f / fmaxf((float)cnt, 2.f)), 3.1416f);
            thr = cosf(r);
        }
        cnts[s] = cnt;
    }
    __syncwarp();

    // exact top-64 by rank-count (ties -> lowest original index); slot = rank
#pragma unroll
    for (int s = 0; s < 2; s++) {
        int pix = 2 * w + s;
        int cnt = min(cnts[s], SCAP);
        for (int t = lane; t < cnt; t += 32) {
            float v = cv[pix][t]; int id = cid[pix][t];
            int rank = 0;
            for (int j = 0; j < cnt; j++) {
                float vj = cv[pix][j];
                int idj = cid[pix][j];
                rank += (vj > v) || (vj == v && idj < id);
            }
            if (rank < Kk) { swv[pix][rank] = v; swid[pix][rank] = id; }
        }
    }
    __syncwarp();

    // attention MLP + softmax pool per pixel (warp-local, 2 logits per lane)
    const float4* __restrict__ los = g_los4 + b * Nn;
#pragma unroll
    for (int s = 0; s < 2; s++) {
        int pix = 2 * w + s;
        float v0 = swv[pix][lane], v1 = swv[pix][lane + 32];
        int   i0 = swid[pix][lane], i1 = swid[pix][lane + 32];
        float x0 = los[i0].w, x1 = los[i1].w;
        float d0 = acosf(fminf(1.f, fmaxf(-1.f, v0)));
        float d1 = acosf(fminf(1.f, fmaxf(-1.f, v1)));
        float l0 = sab2v, l1 = sab2v;
#pragma unroll
        for (int j = 0; j < 32; j++) {
            float h0 = fmaf(x0, sw1x[j], fmaf(d0, sw1d[j], sb1[j]));
            float h1 = fmaf(x1, sw1x[j], fmaf(d1, sw1d[j], sb1[j]));
            l0 = fmaf(fmaxf(h0, 0.f), sw2[j], l0);
            l1 = fmaf(fmaxf(h1, 0.f), sw2[j], l1);
        }
        float mx = fmaxf(l0, l1);
#pragma unroll
        for (int off = 16; off; off >>= 1) mx = fmaxf(mx, __shfl_xor_sync(0xffffffffu, mx, off));
        float e0 = __expf(l0 - mx), e1 = __expf(l1 - mx);
        float sm = e0 + e1;
        float wx = e0 * x0 + e1 * x1;
#pragma unroll
        for (int off = 16; off; off >>= 1) {
            sm += __shfl_xor_sync(0xffffffffu, sm, off);
            wx += __shfl_xor_sync(0xffffffffu, wx, off);
        }
        if (lane == 0) spool[pix] = wx / sm;
    }
    __syncthreads();

    // projection: 16 pixels x 64 features
    for (int i = tid; i < 16 * 64; i += 256) {
        int pix = i >> 6, c = i & 63;
        g_h0[(b * Mm + m0 + pix) * 64 + c] = fmaxf(fmaf(spool[pix], pw[c], pb[c]), 0.f);
    }
}

// ---------------- K3: GNN layer, 32-row tiles (768 blocks), two K=64 phases ----------------
// smem floats: sAT[64][33] @0 (2112), sW[64][64] @2112 (4096), sbias @6208, snbr(int)[256] @6272
#define GNN_SMEMF 6528
__global__ void k_gnn(const float* __restrict__ relw, const float* __restrict__ relb,
                      const float* __restrict__ rootw, int layer, int dir) {
    extern __shared__ float smbuf[];
    float* sAT   = smbuf;                 // [k][r], stride 33 (r < 32)
    float* sW    = smbuf + 2112;          // [k][c], stride 64
    float* sbias = smbuf + 6208;
    int*   snbr  = (int*)(smbuf + 6272);

    const float* hin  = dir ? g_h1 : g_h0;
    float*       hout = dir ? g_h0 : g_h1;

    int tid = threadIdx.x;
    int row0 = blockIdx.x * 32;
    int b = row0 / Mm;
    int m0 = row0 - b * Mm;

    for (int i = tid; i < 4096; i += 256) sW[i] = relw[layer * 4096 + i];
    if (tid < 64) sbias[tid] = relb[layer * 64 + tid];
    if (tid < 256) snbr[tid] = g_nbr[m0 * 8 + tid];
    __syncthreads();
    {
        int c = tid & 63, rq = tid >> 6;
        for (int rr = rq; rr < 32; rr += 4) {
            float a = 0.f;
#pragma unroll
            for (int j = 0; j < 8; j++) a += hin[(b * Mm + snbr[rr * 8 + j]) * 64 + c];
            sAT[c * 33 + rr] = a;
        }
    }
    __syncthreads();

    int tx = tid & 15, ty = tid >> 4;
    int r0 = ty * 2, c0 = tx * 4;
    float acc[2][4];
#pragma unroll
    for (int i = 0; i < 2; i++)
#pragma unroll
        for (int j = 0; j < 4; j++) acc[i][j] = sbias[c0 + j];

#pragma unroll 4
    for (int k = 0; k < 64; k++) {
        float a0 = sAT[k * 33 + r0];
        float a1 = sAT[k * 33 + r0 + 1];
        float4 wv = *(const float4*)&sW[k * 64 + c0];
        acc[0][0] = fmaf(a0, wv.x, acc[0][0]); acc[0][1] = fmaf(a0, wv.y, acc[0][1]);
        acc[0][2] = fmaf(a0, wv.z, acc[0][2]); acc[0][3] = fmaf(a0, wv.w, acc[0][3]);
        acc[1][0] = fmaf(a1, wv.x, acc[1][0]); acc[1][1] = fmaf(a1, wv.y, acc[1][1]);
        acc[1][2] = fmaf(a1, wv.z, acc[1][2]); acc[1][3] = fmaf(a1, wv.w, acc[1][3]);
    }
    __syncthreads();

    for (int i = tid; i < 4096; i += 256) sW[i] = rootw[layer * 4096 + i];
    for (int i = tid; i < 2048; i += 256) {
        int r = i >> 6, k = i & 63;
        sAT[k * 33 + r] = hin[row0 * 64 + i];
    }
    __syncthreads();

#pragma unroll 4
    for (int k = 0; k < 64; k++) {
        float a0 = sAT[k * 33 + r0];
        float a1 = sAT[k * 33 + r0 + 1];
        float4 wv = *(const float4*)&sW[k * 64 + c0];
        acc[0][0] = fmaf(a0, wv.x, acc[0][0]); acc[0][1] = fmaf(a0, wv.y, acc[0][1]);
        acc[0][2] = fmaf(a0, wv.z, acc[0][2]); acc[0][3] = fmaf(a0, wv.w, acc[0][3]);
        acc[1][0] = fmaf(a1, wv.x, acc[1][0]); acc[1][1] = fmaf(a1, wv.y, acc[1][1]);
        acc[1][2] = fmaf(a1, wv.z, acc[1][2]); acc[1][3] = fmaf(a1, wv.w, acc[1][3]);
    }

#pragma unroll
    for (int i = 0; i < 2; i++) {
        float4 o;
        o.x = fmaxf(acc[i][0], 0.f);
        o.y = fmaxf(acc[i][1], 0.f);
        o.z = fmaxf(acc[i][2], 0.f);
        o.w = fmaxf(acc[i][3], 0.f);
        *(float4*)&hout[(row0 + r0 + i) * 64 + c0] = o;
    }
}

// ---------------- K4a: partial mean-pool reduction ----------------
__global__ void k_red() {
    __shared__ float part[128];
    int tid = threadIdx.x;
    int blk = blockIdx.x;
    int b = blk / 96, seg = blk % 96;
    int c = tid & 63, half = tid >> 6;
    float a = 0.f;
    int mbase = seg * 128;
    for (int i = half; i < 128; i += 2)
        a += g_h1[(b * Mm + mbase + i) * 64 + c];
    part[tid] = a;
    __syncthreads();
    if (tid < 64) g_part[(b * 96 + seg) * 64 + c] = part[tid] + part[tid + 64];
}

// ---------------- K4b: final reduce + output MLP ----------------
__global__ void k_out(const float* __restrict__ ow1, const float* __restrict__ ob1,
                      const float* __restrict__ ow2, const float* __restrict__ ob2,
                      float* __restrict__ out) {
    __shared__ float sgf[64], shid[64];
    int tid = threadIdx.x;
    int b = blockIdx.x;
    if (tid < 64) {
        float a = 0.f;
        for (int s = 0; s < 96; s++) a += g_part[(b * 96 + s) * 64 + tid];
        sgf[tid] = a * (1.f / (float)Mm);
    }
    __syncthreads();
    if (tid < 64) {
        float a = ob1[tid];
        for (int k = 0; k < 64; k++) a = fmaf(sgf[k], ow1[k * 64 + tid], a);
        shid[tid] = fmaxf(a, 0.f);
    }
    __syncthreads();
    if (tid < NCc) {
        float a = ob2[tid];
        for (int k = 0; k < 64; k++) a = fmaf(shid[k], ow2[k * NCc + tid], a);
        out[b * NCc + tid] = a;
    }
}

// ---------------- launch ----------------
extern "C" void kernel_launch(void* const* d_in, const int* in_sizes, int n_in,
                              void* d_out, int out_size) {
    const float* xxx  = (const float*)d_in[0];
    const float* ptp  = (const float*)d_in[1];
    const float* aw1  = (const float*)d_in[2];
    const float* ab1  = (const float*)d_in[3];
    const float* aw2  = (const float*)d_in[4];
    const float* ab2  = (const float*)d_in[5];
    const float* pw   = (const float*)d_in[6];
    const float* pb   = (const float*)d_in[7];
    const float* relw = (const float*)d_in[8];
    const float* relb = (const float*)d_in[9];
    const float* rootw= (const float*)d_in[10];
    const float* ow1  = (const float*)d_in[11];
    const float* ob1  = (const float*)d_in[12];
    const float* ow2  = (const float*)d_in[13];
    const float* ob2  = (const float*)d_in[14];
    float* out = (float*)d_out;

    (void)in_sizes; (void)n_in; (void)out_size;

    k_pre<<<48, 256>>>(xxx, ptp);             // my idx 0 (harness pre-launches 2 -> overall 2)
    k_sort<<<3, 256>>>(xxx, ptp);             // my idx 1 -> overall 3
    k_knn<<<Mm / 16, 256>>>(ptp);             // my idx 2 -> overall 4
    k_samp<<<Bq * 768, 256>>>(ptp, aw1, ab1, aw2, ab2, pw, pb);  // my idx 3 -> overall 5 <- ncu

    const int SM3 = GNN_SMEMF * 4;
    cudaFuncSetAttribute(k_gnn, cudaFuncAttributeMaxDynamicSharedMemorySize, SM3);
    k_gnn<<<768, 256, SM3>>>(relw, relb, rootw, 0, 0); // g_h0 -> g_h1
    k_gnn<<<768, 256, SM3>>>(relw, relb, rootw, 1, 1); // g_h1 -> g_h0
    k_gnn<<<768, 256, SM3>>>(relw, relb, rootw, 2, 0); // g_h0 -> g_h1

    k_red<<<Bq * 96, 128>>>();
    k_out<<<Bq, 256>>>(ow1, ob1, ow2, ob2, out);
}

// round 16
// speedup vs baseline: 5.1094x; 1.3339x over previous
#include <cuda_runtime.h>
#include <math.h>

#define Bq 2
#define Nn 4096
#define Mm 12288
#define Kk 64
#define Hh 64
#define GKk 8
#define NCc 200
#define SCAP 192
#define KCAP 48
#define NBAND 64
#define IBW (NBAND / 3.14159265f)

// ---------------- scratch (static device globals; no allocation) ----------------
__device__ float4 g_los4[Bq*Nn];    // x,y,z,feat (original order)
__device__ float4 g_pix4[Mm];       // x,y,z,|p|^2 (original order)
__device__ float4 g_los4s[Bq*Nn];   // theta-banded: x,y,z,origidx
__device__ float4 g_pix4s[Mm];      // theta-banded: x,y,z,origidx
__device__ int    g_loff[Bq*(NBAND+1)];
__device__ int    g_poff[NBAND+1];
__device__ int    g_nbr[Mm*GKk];
__device__ float  g_h0[Bq*Mm*Hh];
__device__ float  g_h1[Bq*Mm*Hh];
__device__ float  g_part[Bq*96*Hh];

__device__ __forceinline__ unsigned fkey(float f) {
    unsigned u = __float_as_uint(f);
    return (u & 0x80000000u) ? ~u : (u | 0x80000000u);
}
__device__ __forceinline__ float fkeyinv(unsigned k) {
    unsigned u = (k & 0x80000000u) ? (k & 0x7FFFFFFFu) : ~k;
    return __uint_as_float(u);
}

// ---------------- K0: precompute packed unit vectors ----------------
__global__ void k_pre(const float* __restrict__ xxx, const float* __restrict__ ptp) {
    int i = blockIdx.x * blockDim.x + threadIdx.x;
    if (i < Bq * Nn) {
        int b = i / Nn, n = i - b * Nn;
        float th = xxx[b * 3 * Nn + n];
        float ph = xxx[b * 3 * Nn + Nn + n];
        float ft = xxx[b * 3 * Nn + 2 * Nn + n];
        float st, ct, sp, cp;
        sincosf(th, &st, &ct);
        sincosf(ph, &sp, &cp);
        g_los4[i] = make_float4(st * cp, st * sp, ct, ft);
    }
    if (i < Mm) {
        float th = ptp[2 * i], ph = ptp[2 * i + 1];
        float st, ct, sp, cp;
        sincosf(th, &st, &ct);
        sincosf(ph, &sp, &cp);
        float x = st * cp, y = st * sp, z = ct;
        g_pix4[i] = make_float4(x, y, z, x * x + y * y + z * z);
    }
}

// ---------------- K0b: theta-band counting sort (los per batch + pixels) ----------------
__global__ void k_sort(const float* __restrict__ xxx, const float* __restrict__ ptp) {
    __shared__ int hist[NBAND], woff[NBAND];
    int tid = threadIdx.x;
    int blk = blockIdx.x;           // 0,1: los batch; 2: pixels
    if (tid < NBAND) hist[tid] = 0;
    __syncthreads();
    if (blk < Bq) {
        int b = blk;
        const float* th = xxx + b * 3 * Nn;
        for (int i = tid; i < Nn; i += 256) {
            int band = min(NBAND - 1, max(0, (int)(th[i] * IBW)));
            atomicAdd(&hist[band], 1);
        }
        __syncthreads();
        if (tid == 0) {
            int s = 0;
            for (int k = 0; k < NBAND; k++) {
                woff[k] = s;
                g_loff[b * (NBAND + 1) + k] = s;
                s += hist[k];
            }
            g_loff[b * (NBAND + 1) + NBAND] = s;
        }
        __syncthreads();
        for (int i = tid; i < Nn; i += 256) {
            int band = min(NBAND - 1, max(0, (int)(th[i] * IBW)));
            int slot = atomicAdd(&woff[band], 1);
            float4 l = g_los4[b * Nn + i];
            g_los4s[b * Nn + slot] = make_float4(l.x, l.y, l.z, __int_as_float(i));
        }
    } else {
        for (int i = tid; i < Mm; i += 256) {
            int band = min(NBAND - 1, max(0, (int)(ptp[2 * i] * IBW)));
            atomicAdd(&hist[band], 1);
        }
        __syncthreads();
        if (tid == 0) {
            int s = 0;
            for (int k = 0; k < NBAND; k++) {
                woff[k] = s;
                g_poff[k] = s;
                s += hist[k];
            }
            g_poff[NBAND] = s;
        }
        __syncthreads();
        for (int i = tid; i < Mm; i += 256) {
            int band = min(NBAND - 1, max(0, (int)(ptp[2 * i] * IBW)));
            int slot = atomicAdd(&woff[band], 1);
            float4 p = g_pix4[i];
            g_pix4s[slot] = make_float4(p.x, p.y, p.z, __int_as_float(i));
        }
    }
}

// ---------------- K1: kNN graph (banded threshold-collect + exact rank top-8) ----------------
__global__ void __launch_bounds__(256, 2)
k_knn(const float* __restrict__ ptp) {
    __shared__ float kv[16][KCAP];
    __shared__ int   kid[16][KCAP];

    int tid = threadIdx.x, lane = tid & 31, w = tid >> 5;
    unsigned ltm = (1u << lane) - 1u;
    int cnts[2];

#pragma unroll
    for (int s = 0; s < 2; s++) {
        int pix = 2 * w + s;
        int gi = blockIdx.x * 16 + pix;
        float4 p = g_pix4[gi];
        float th = ptp[2 * gi];
        float sn = sqrtf(p.x * p.x + p.y * p.y);
        float r = fmaxf(0.00614f, 0.1108f * sqrtf(sn));
        float thr = 2.f * cosf(r) - 1.f;
        int cnt = 0;
        for (int att = 0; att < 24; att++) {
            int lo = max(0, (int)((th - r) * IBW) - 1);
            int hi = min(NBAND - 1, (int)((th + r) * IBW) + 1);
            int n0 = g_poff[lo], n1 = g_poff[hi + 1];
            int base = 0;
            for (int nb = n0; nb < n1; nb += 32) {
                int n = nb + lane;
                bool valid = n < n1;
                float4 cd = g_pix4s[valid ? n : (n1 - 1)];
                float cq = fmaf(cd.x, cd.x, fmaf(cd.y, cd.y, cd.z * cd.z));
                int oid = __float_as_int(cd.w);
                float sc = 2.f * fmaf(p.x, cd.x, fmaf(p.y, cd.y, p.z * cd.z)) - cq;
                bool h = valid && (sc > thr) && (oid != gi);
                unsigned mk = __ballot_sync(0xffffffffu, h);
                if (h) {
                    int pos = base + __popc(mk & ltm);
                    if (pos < KCAP) { kv[pix][pos] = sc; kid[pix][pos] = oid; }
                }
                base += __popc(mk);
            }
            cnt = base;
            if (cnt >= GKk && cnt <= KCAP) break;
            r = fminf(r * sqrtf(24.f / fmaxf((float)cnt, 2.f)), 3.1416f);
            thr = 2.f * cosf(r) - 1.f;
        }
        cnts[s] = cnt;
    }
    __syncwarp();

#pragma unroll
    for (int s = 0; s < 2; s++) {
        int pix = 2 * w + s;
        int gpix = blockIdx.x * 16 + pix;
        int cnt = min(cnts[s], KCAP);
        for (int t = lane; t < cnt; t += 32) {
            float v = kv[pix][t]; int id = kid[pix][t];
            int rank = 0;
            for (int j2 = 0; j2 < cnt; j2++) {
                float vj = kv[pix][j2];
                int idj = kid[pix][j2];
                rank += (vj > v) || (vj == v && idj < id);
            }
            if (rank < GKk) g_nbr[gpix * GKk + rank] = id;
        }
    }
}

// ---------------- K2: sparse sampler (banded scan + bisection top-64) ----------------
__global__ void __launch_bounds__(256, 2)
k_samp(const float* __restrict__ ptp,
       const float* __restrict__ aw1, const float* __restrict__ ab1,
       const float* __restrict__ aw2, const float* __restrict__ ab2,
       const float* __restrict__ pw,  const float* __restrict__ pb) {
    __shared__ float  cv[16][SCAP];
    __shared__ int    cid[16][SCAP];
    __shared__ float  swv[16][Kk];
    __shared__ int    swid[16][Kk];
    __shared__ float  spool[16];
    __shared__ float  sw1x[32], sw1d[32], sb1[32], sw2[32];
    __shared__ float  sab2v;

    int tid = threadIdx.x, lane = tid & 31, w = tid >> 5;
    int b  = blockIdx.x / 768;
    int m0 = (blockIdx.x % 768) * 16;
    const float4* __restrict__ loss = g_los4s + b * Nn;
    const int* __restrict__ loff = g_loff + b * (NBAND + 1);
    unsigned ltm = (1u << lane) - 1u;

    if (tid < 32) {
        sw1x[tid] = aw1[tid];
        sw1d[tid] = aw1[32 + tid];
        sb1[tid]  = ab1[tid];
        sw2[tid]  = aw2[tid];
    }
    if (tid == 0) sab2v = ab2[0];
    __syncthreads();

    int cnts[2];
    float thrs[2];
#pragma unroll
    for (int s = 0; s < 2; s++) {
        int pix = 2 * w + s;
        int gm = m0 + pix;
        float4 q = g_pix4[gm];
        float th = ptp[2 * gm];
        float sn = sqrtf(q.x * q.x + q.y * q.y);
        float r = fmaxf(0.0859f, 0.4145f * sqrtf(sn));
        float thr = cosf(r);
        int cnt = 0;
        for (int att = 0; att < 24; att++) {
            int lo = max(0, (int)((th - r) * IBW) - 1);
            int hi = min(NBAND - 1, (int)((th + r) * IBW) + 1);
            int n0 = loff[lo], n1 = loff[hi + 1];
            int base = 0;
            for (int nb = n0; nb < n1; nb += 32) {
                int n = nb + lane;
                bool valid = n < n1;
                float4 l = loss[valid ? n : (n1 - 1)];
                float v = fmaf(l.x, q.x, fmaf(l.y, q.y, l.z * q.z));
                bool h = valid && (v > thr);
                unsigned mk = __ballot_sync(0xffffffffu, h);
                if (h) {
                    int pos = base + __popc(mk & ltm);
                    if (pos < SCAP) { cv[pix][pos] = v; cid[pix][pos] = __float_as_int(l.w); }
                }
                base += __popc(mk);
            }
            cnt = base;
            if (cnt >= Kk && cnt <= SCAP) break;
            r = fminf(r * sqrtf(112.f / fmaxf((float)cnt, 2.f)), 3.1416f);
            thr = cosf(r);
        }
        cnts[s] = cnt;
        thrs[s] = thr;
    }
    __syncwarp();

    // exact top-64 via register cache + integer bisection on monotone key
#pragma unroll
    for (int s = 0; s < 2; s++) {
        int pix = 2 * w + s;
        int cnt = min(cnts[s], SCAP);
        // cache candidates (<=6 per lane)
        float rv[6]; int rid[6]; unsigned kk[6];
#pragma unroll
        for (int i = 0; i < 6; i++) {
            int t = lane + 32 * i;
            bool vld = t < cnt;
            rv[i]  = vld ? cv[pix][t] : 0.f;
            rid[i] = vld ? cid[pix][t] : 0x7FFFFFFF;
            kk[i]  = vld ? fkey(rv[i]) : 0u;   // 0 never counted (all real keys > 0)
        }
        // bisect: T = max key with count(key >= T) >= 64
        unsigned lo = fkey(thrs[s]), hi = fkey(1.5f);
        while (lo < hi) {
            unsigned mid = lo + ((hi - lo + 1u) >> 1);
            int c = 0;
#pragma unroll
            for (int i = 0; i < 6; i++) c += (kk[i] >= mid);
            int tot = __reduce_add_sync(0xffffffffu, c);
            if (tot >= Kk) lo = mid; else hi = mid - 1u;
        }
        unsigned T = lo;
        // collect key > T (deterministic ballot order)
        int base = 0;
#pragma unroll
        for (int i = 0; i < 6; i++) {
            bool h = kk[i] > T;
            unsigned mk = __ballot_sync(0xffffffffu, h);
            if (h) {
                int pos = base + __popc(mk & ltm);
                swv[pix][pos] = rv[i]; swid[pix][pos] = rid[i];
            }
            base += __popc(mk);
        }
        int cgt = base;          // < 64 by construction
        int need = Kk - cgt;
        // ties: key == T, lowest ids win (usually 1 element)
        int ntb = 0;
#pragma unroll
        for (int i = 0; i < 6; i++) {
            bool e = kk[i] == T;
            unsigned mk = __ballot_sync(0xffffffffu, e);
            if (e) {
                int pos = ntb + __popc(mk & ltm);
                cid[pix][pos] = rid[i];   // cv/cid rows now free scratch
            }
            ntb += __popc(mk);
        }
        float Tval = fkeyinv(T);
        for (int t = lane; t < ntb; t += 32) {
            int id = cid[pix][t];
            int rank = 0;
            for (int j = 0; j < ntb; j++) rank += (cid[pix][j] < id);
            if (rank < need) { swv[pix][cgt + rank] = Tval; swid[pix][cgt + rank] = id; }
        }
    }
    __syncwarp();

    // attention MLP + softmax pool per pixel (warp-local, 2 logits per lane)
    const float4* __restrict__ los = g_los4 + b * Nn;
#pragma unroll
    for (int s = 0; s < 2; s++) {
        int pix = 2 * w + s;
        float v0 = swv[pix][lane], v1 = swv[pix][lane + 32];
        int   i0 = swid[pix][lane], i1 = swid[pix][lane + 32];
        float x0 = los[i0].w, x1 = los[i1].w;
        float d0 = acosf(fminf(1.f, fmaxf(-1.f, v0)));
        float d1 = acosf(fminf(1.f, fmaxf(-1.f, v1)));
        float l0 = sab2v, l1 = sab2v;
#pragma unroll
        for (int j = 0; j < 32; j++) {
            float h0 = fmaf(x0, sw1x[j], fmaf(d0, sw1d[j], sb1[j]));
            float h1 = fmaf(x1, sw1x[j], fmaf(d1, sw1d[j], sb1[j]));
            l0 = fmaf(fmaxf(h0, 0.f), sw2[j], l0);
            l1 = fmaf(fmaxf(h1, 0.f), sw2[j], l1);
        }
        float mx = fmaxf(l0, l1);
#pragma unroll
        for (int off = 16; off; off >>= 1) mx = fmaxf(mx, __shfl_xor_sync(0xffffffffu, mx, off));
        float e0 = __expf(l0 - mx), e1 = __expf(l1 - mx);
        float sm = e0 + e1;
        float wx = e0 * x0 + e1 * x1;
#pragma unroll
        for (int off = 16; off; off >>= 1) {
            sm += __shfl_xor_sync(0xffffffffu, sm, off);
            wx += __shfl_xor_sync(0xffffffffu, wx, off);
        }
        if (lane == 0) spool[pix] = wx / sm;
    }
    __syncthreads();

    // projection: 16 pixels x 64 features
    for (int i = tid; i < 16 * 64; i += 256) {
        int pix = i >> 6, c = i & 63;
        g_h0[(b * Mm + m0 + pix) * 64 + c] = fmaxf(fmaf(spool[pix], pw[c], pb[c]), 0.f);
    }
}

// ---------------- K3: GNN layer, 32-row tiles (768 blocks), two K=64 phases ----------------
// smem floats: sAT[64][33] @0 (2112), sW[64][64] @2112 (4096), sbias @6208, snbr(int)[256] @6272
#define GNN_SMEMF 6528
__global__ void k_gnn(const float* __restrict__ relw, const float* __restrict__ relb,
                      const float* __restrict__ rootw, int layer, int dir) {
    extern __shared__ float smbuf[];
    float* sAT   = smbuf;                 // [k][r], stride 33 (r < 32)
    float* sW    = smbuf + 2112;          // [k][c], stride 64
    float* sbias = smbuf + 6208;
    int*   snbr  = (int*)(smbuf + 6272);

    const float* hin  = dir ? g_h1 : g_h0;
    float*       hout = dir ? g_h0 : g_h1;

    int tid = threadIdx.x;
    int row0 = blockIdx.x * 32;
    int b = row0 / Mm;
    int m0 = row0 - b * Mm;

    for (int i = tid; i < 4096; i += 256) sW[i] = relw[layer * 4096 + i];
    if (tid < 64) sbias[tid] = relb[layer * 64 + tid];
    if (tid < 256) snbr[tid] = g_nbr[m0 * 8 + tid];
    __syncthreads();
    {
        int c = tid & 63, rq = tid >> 6;
        for (int rr = rq; rr < 32; rr += 4) {
            float a = 0.f;
#pragma unroll
            for (int j = 0; j < 8; j++) a += hin[(b * Mm + snbr[rr * 8 + j]) * 64 + c];
            sAT[c * 33 + rr] = a;
        }
    }
    __syncthreads();

    int tx = tid & 15, ty = tid >> 4;
    int r0 = ty * 2, c0 = tx * 4;
    float acc[2][4];
#pragma unroll
    for (int i = 0; i < 2; i++)
#pragma unroll
        for (int j = 0; j < 4; j++) acc[i][j] = sbias[c0 + j];

#pragma unroll 4
    for (int k = 0; k < 64; k++) {
        float a0 = sAT[k * 33 + r0];
        float a1 = sAT[k * 33 + r0 + 1];
        float4 wv = *(const float4*)&sW[k * 64 + c0];
        acc[0][0] = fmaf(a0, wv.x, acc[0][0]); acc[0][1] = fmaf(a0, wv.y, acc[0][1]);
        acc[0][2] = fmaf(a0, wv.z, acc[0][2]); acc[0][3] = fmaf(a0, wv.w, acc[0][3]);
        acc[1][0] = fmaf(a1, wv.x, acc[1][0]); acc[1][1] = fmaf(a1, wv.y, acc[1][1]);
        acc[1][2] = fmaf(a1, wv.z, acc[1][2]); acc[1][3] = fmaf(a1, wv.w, acc[1][3]);
    }
    __syncthreads();

    for (int i = tid; i < 4096; i += 256) sW[i] = rootw[layer * 4096 + i];
    for (int i = tid; i < 2048; i += 256) {
        int r = i >> 6, k = i & 63;
        sAT[k * 33 + r] = hin[row0 * 64 + i];
    }
    __syncthreads();

#pragma unroll 4
    for (int k = 0; k < 64; k++) {
        float a0 = sAT[k * 33 + r0];
        float a1 = sAT[k * 33 + r0 + 1];
        float4 wv = *(const float4*)&sW[k * 64 + c0];
        acc[0][0] = fmaf(a0, wv.x, acc[0][0]); acc[0][1] = fmaf(a0, wv.y, acc[0][1]);
        acc[0][2] = fmaf(a0, wv.z, acc[0][2]); acc[0][3] = fmaf(a0, wv.w, acc[0][3]);
        acc[1][0] = fmaf(a1, wv.x, acc[1][0]); acc[1][1] = fmaf(a1, wv.y, acc[1][1]);
        acc[1][2] = fmaf(a1, wv.z, acc[1][2]); acc[1][3] = fmaf(a1, wv.w, acc[1][3]);
    }

#pragma unroll
    for (int i = 0; i < 2; i++) {
        float4 o;
        o.x = fmaxf(acc[i][0], 0.f);
        o.y = fmaxf(acc[i][1], 0.f);
        o.z = fmaxf(acc[i][2], 0.f);
        o.w = fmaxf(acc[i][3], 0.f);
        *(float4*)&hout[(row0 + r0 + i) * 64 + c0] = o;
    }
}

// ---------------- K4a: partial mean-pool reduction ----------------
__global__ void k_red() {
    __shared__ float part[128];
    int tid = threadIdx.x;
    int blk = blockIdx.x;
    int b = blk / 96, seg = blk % 96;
    int c = tid & 63, half = tid >> 6;
    float a = 0.f;
    int mbase = seg * 128;
    for (int i = half; i < 128; i += 2)
        a += g_h1[(b * Mm + mbase + i) * 64 + c];
    part[tid] = a;
    __syncthreads();
    if (tid < 64) g_part[(b * 96 + seg) * 64 + c] = part[tid] + part[tid + 64];
}

// ---------------- K4b: final reduce + output MLP ----------------
__global__ void k_out(const float* __restrict__ ow1, const float* __restrict__ ob1,
                      const float* __restrict__ ow2, const float* __restrict__ ob2,
                      float* __restrict__ out) {
    __shared__ float sgf[64], shid[64];
    int tid = threadIdx.x;
    int b = blockIdx.x;
    if (tid < 64) {
        float a = 0.f;
        for (int s = 0; s < 96; s++) a += g_part[(b * 96 + s) * 64 + tid];
        sgf[tid] = a * (1.f / (float)Mm);
    }
    __syncthreads();
    if (tid < 64) {
        float a = ob1[tid];
        for (int k = 0; k < 64; k++) a = fmaf(sgf[k], ow1[k * 64 + tid], a);
        shid[tid] = fmaxf(a, 0.f);
    }
    __syncthreads();
    if (tid < NCc) {
        float a = ob2[tid];
        for (int k = 0; k < 64; k++) a = fmaf(shid[k], ow2[k * NCc + tid], a);
        out[b * NCc + tid] = a;
    }
}

// ---------------- launch ----------------
extern "C" void kernel_launch(void* const* d_in, const int* in_sizes, int n_in,
                              void* d_out, int out_size) {
    const float* xxx  = (const float*)d_in[0];
    const float* ptp  = (const float*)d_in[1];
    const float* aw1  = (const float*)d_in[2];
    const float* ab1  = (const float*)d_in[3];
    const float* aw2  = (const float*)d_in[4];
    const float* ab2  = (const float*)d_in[5];
    const float* pw   = (const float*)d_in[6];
    const float* pb   = (const float*)d_in[7];
    const float* relw = (const float*)d_in[8];
    const float* relb = (const float*)d_in[9];
    const float* rootw= (const float*)d_in[10];
    const float* ow1  = (const float*)d_in[11];
    const float* ob1  = (const float*)d_in[12];
    const float* ow2  = (const float*)d_in[13];
    const float* ob2  = (const float*)d_in[14];
    float* out = (float*)d_out;

    (void)in_sizes; (void)n_in; (void)out_size;

    k_pre<<<48, 256>>>(xxx, ptp);             // my idx 0 (harness pre-launches 2 -> overall 2)
    k_sort<<<3, 256>>>(xxx, ptp);             // my idx 1 -> overall 3
    k_knn<<<Mm / 16, 256>>>(ptp);             // my idx 2 -> overall 4
    k_samp<<<Bq * 768, 256>>>(ptp, aw1, ab1, aw2, ab2, pw, pb);  // my idx 3 -> overall 5 <- ncu

    const int SM3 = GNN_SMEMF * 4;
    cudaFuncSetAttribute(k_gnn, cudaFuncAttributeMaxDynamicSharedMemorySize, SM3);
    k_gnn<<<768, 256, SM3>>>(relw, relb, rootw, 0, 0); // g_h0 -> g_h1
    k_gnn<<<768, 256, SM3>>>(relw, relb, rootw, 1, 1); // g_h1 -> g_h0
    k_gnn<<<768, 256, SM3>>>(relw, relb, rootw, 2, 0); // g_h0 -> g_h1

    k_red<<<Bq * 96, 128>>>();
    k_out<<<Bq, 256>>>(ow1, ob1, ow2, ob2, out);
}

// round 17
// speedup vs baseline: 5.4000x; 1.0569x over previous
#include <cuda_runtime.h>
#include <math.h>

#define Bq 2
#define Nn 4096
#define Mm 12288
#define Kk 64
#define Hh 64
#define GKk 8
#define NCc 200
#define SCAP 192
#define KCAP 48
#define NBAND 64
#define IBW (NBAND / 3.14159265f)

// ---------------- scratch (static device globals; no allocation) ----------------
__device__ float4 g_los4[Bq*Nn];    // x,y,z,feat (original order)
__device__ float4 g_pix4[Mm];       // x,y,z,|p|^2 (original order)
__device__ float4 g_los4s[Bq*Nn];   // theta-banded: x,y,z,origidx
__device__ float4 g_pix4s[Mm];      // theta-banded: x,y,z,origidx
__device__ int    g_loff[Bq*(NBAND+1)];
__device__ int    g_poff[NBAND+1];
__device__ int    g_nbr[Mm*GKk];
__device__ float  g_h0[Bq*Mm*Hh];
__device__ float  g_h1[Bq*Mm*Hh];
__device__ float  g_part[Bq*96*Hh];

__device__ __forceinline__ unsigned fkey(float f) {
    unsigned u = __float_as_uint(f);
    return (u & 0x80000000u) ? ~u : (u | 0x80000000u);
}
__device__ __forceinline__ float fkeyinv(unsigned k) {
    unsigned u = (k & 0x80000000u) ? (k & 0x7FFFFFFFu) : ~k;
    return __uint_as_float(u);
}

// ---------------- K0: precompute packed unit vectors ----------------
__global__ void k_pre(const float* __restrict__ xxx, const float* __restrict__ ptp) {
    int i = blockIdx.x * blockDim.x + threadIdx.x;
    if (i < Bq * Nn) {
        int b = i / Nn, n = i - b * Nn;
        float th = xxx[b * 3 * Nn + n];
        float ph = xxx[b * 3 * Nn + Nn + n];
        float ft = xxx[b * 3 * Nn + 2 * Nn + n];
        float st, ct, sp, cp;
        sincosf(th, &st, &ct);
        sincosf(ph, &sp, &cp);
        g_los4[i] = make_float4(st * cp, st * sp, ct, ft);
    }
    if (i < Mm) {
        float th = ptp[2 * i], ph = ptp[2 * i + 1];
        float st, ct, sp, cp;
        sincosf(th, &st, &ct);
        sincosf(ph, &sp, &cp);
        float x = st * cp, y = st * sp, z = ct;
        g_pix4[i] = make_float4(x, y, z, x * x + y * y + z * z);
    }
}

// ---------------- K0b: theta-band counting sort (los per batch + pixels) ----------------
__global__ void k_sort(const float* __restrict__ xxx, const float* __restrict__ ptp) {
    __shared__ int hist[NBAND], woff[NBAND];
    int tid = threadIdx.x;
    int blk = blockIdx.x;           // 0,1: los batch; 2: pixels
    if (tid < NBAND) hist[tid] = 0;
    __syncthreads();
    if (blk < Bq) {
        int b = blk;
        const float* th = xxx + b * 3 * Nn;
        for (int i = tid; i < Nn; i += 256) {
            int band = min(NBAND - 1, max(0, (int)(th[i] * IBW)));
            atomicAdd(&hist[band], 1);
        }
        __syncthreads();
        if (tid == 0) {
            int s = 0;
            for (int k = 0; k < NBAND; k++) {
                woff[k] = s;
                g_loff[b * (NBAND + 1) + k] = s;
                s += hist[k];
            }
            g_loff[b * (NBAND + 1) + NBAND] = s;
        }
        __syncthreads();
        for (int i = tid; i < Nn; i += 256) {
            int band = min(NBAND - 1, max(0, (int)(th[i] * IBW)));
            int slot = atomicAdd(&woff[band], 1);
            float4 l = g_los4[b * Nn + i];
            g_los4s[b * Nn + slot] = make_float4(l.x, l.y, l.z, __int_as_float(i));
        }
    } else {
        for (int i = tid; i < Mm; i += 256) {
            int band = min(NBAND - 1, max(0, (int)(ptp[2 * i] * IBW)));
            atomicAdd(&hist[band], 1);
        }
        __syncthreads();
        if (tid == 0) {
            int s = 0;
            for (int k = 0; k < NBAND; k++) {
                woff[k] = s;
                g_poff[k] = s;
                s += hist[k];
            }
            g_poff[NBAND] = s;
        }
        __syncthreads();
        for (int i = tid; i < Mm; i += 256) {
            int band = min(NBAND - 1, max(0, (int)(ptp[2 * i] * IBW)));
            int slot = atomicAdd(&woff[band], 1);
            float4 p = g_pix4[i];
            g_pix4s[slot] = make_float4(p.x, p.y, p.z, __int_as_float(i));
        }
    }
}

// ---------------- K1: kNN graph (banded threshold-collect + exact rank top-8) ----------------
__global__ void __launch_bounds__(256, 2)
k_knn(const float* __restrict__ ptp) {
    __shared__ float kv[16][KCAP];
    __shared__ int   kid[16][KCAP];

    int tid = threadIdx.x, lane = tid & 31, w = tid >> 5;
    unsigned ltm = (1u << lane) - 1u;
    int cnts[2];

#pragma unroll
    for (int s = 0; s < 2; s++) {
        int pix = 2 * w + s;
        int gi = blockIdx.x * 16 + pix;
        float4 p = g_pix4[gi];
        float th = ptp[2 * gi];
        float sn = sqrtf(p.x * p.x + p.y * p.y);
        float r = fmaxf(0.00614f, 0.1108f * sqrtf(sn));
        float thr = 2.f * cosf(r) - 1.f;
        int cnt = 0;
        for (int att = 0; att < 24; att++) {
            int lo = max(0, (int)((th - r) * IBW) - 1);
            int hi = min(NBAND - 1, (int)((th + r) * IBW) + 1);
            int n0 = g_poff[lo], n1 = g_poff[hi + 1];
            int base = 0;
            for (int nb = n0; nb < n1; nb += 32) {
                int n = nb + lane;
                bool valid = n < n1;
                float4 cd = g_pix4s[valid ? n : (n1 - 1)];
                float cq = fmaf(cd.x, cd.x, fmaf(cd.y, cd.y, cd.z * cd.z));
                int oid = __float_as_int(cd.w);
                float sc = 2.f * fmaf(p.x, cd.x, fmaf(p.y, cd.y, p.z * cd.z)) - cq;
                bool h = valid && (sc > thr) && (oid != gi);
                unsigned mk = __ballot_sync(0xffffffffu, h);
                if (h) {
                    int pos = base + __popc(mk & ltm);
                    if (pos < KCAP) { kv[pix][pos] = sc; kid[pix][pos] = oid; }
                }
                base += __popc(mk);
            }
            cnt = base;
            if (cnt >= GKk && cnt <= KCAP) break;
            r = fminf(r * sqrtf(24.f / fmaxf((float)cnt, 2.f)), 3.1416f);
            thr = 2.f * cosf(r) - 1.f;
        }
        cnts[s] = cnt;
    }
    __syncwarp();

#pragma unroll
    for (int s = 0; s < 2; s++) {
        int pix = 2 * w + s;
        int gpix = blockIdx.x * 16 + pix;
        int cnt = min(cnts[s], KCAP);
        for (int t = lane; t < cnt; t += 32) {
            float v = kv[pix][t]; int id = kid[pix][t];
            int rank = 0;
            for (int j2 = 0; j2 < cnt; j2++) {
                float vj = kv[pix][j2];
                int idj = kid[pix][j2];
                rank += (vj > v) || (vj == v && idj < id);
            }
            if (rank < GKk) g_nbr[gpix * GKk + rank] = id;
        }
    }
}

// ---------------- K2: sparse sampler (banded scan + early-exit bisection top-64) ----------------
__global__ void __launch_bounds__(256, 3)
k_samp(const float* __restrict__ ptp,
       const float* __restrict__ aw1, const float* __restrict__ ab1,
       const float* __restrict__ aw2, const float* __restrict__ ab2,
       const float* __restrict__ pw,  const float* __restrict__ pb) {
    __shared__ float  cv[16][SCAP];
    __shared__ int    cid[16][SCAP];
    __shared__ float  swv[16][Kk];
    __shared__ int    swid[16][Kk];
    __shared__ float  spool[16];
    __shared__ float  sw1x[32], sw1d[32], sb1[32], sw2[32];
    __shared__ float  sab2v;

    int tid = threadIdx.x, lane = tid & 31, w = tid >> 5;
    int b  = blockIdx.x / 768;
    int m0 = (blockIdx.x % 768) * 16;
    const float4* __restrict__ loss = g_los4s + b * Nn;
    const int* __restrict__ loff = g_loff + b * (NBAND + 1);
    unsigned ltm = (1u << lane) - 1u;

    if (tid < 32) {
        sw1x[tid] = aw1[tid];
        sw1d[tid] = aw1[32 + tid];
        sb1[tid]  = ab1[tid];
        sw2[tid]  = aw2[tid];
    }
    if (tid == 0) sab2v = ab2[0];
    __syncthreads();

    int cnts[2];
    float thrs[2];
#pragma unroll
    for (int s = 0; s < 2; s++) {
        int pix = 2 * w + s;
        int gm = m0 + pix;
        float4 q = g_pix4[gm];
        float th = ptp[2 * gm];
        float sn = sqrtf(q.x * q.x + q.y * q.y);
        float r = fmaxf(0.0859f, 0.4145f * sqrtf(sn));
        float thr = cosf(r);
        int cnt = 0;
        for (int att = 0; att < 24; att++) {
            int lo = max(0, (int)((th - r) * IBW) - 1);
            int hi = min(NBAND - 1, (int)((th + r) * IBW) + 1);
            int n0 = loff[lo], n1 = loff[hi + 1];
            int base = 0;
            for (int nb = n0; nb < n1; nb += 32) {
                int n = nb + lane;
                bool valid = n < n1;
                float4 l = loss[valid ? n : (n1 - 1)];
                float v = fmaf(l.x, q.x, fmaf(l.y, q.y, l.z * q.z));
                bool h = valid && (v > thr);
                unsigned mk = __ballot_sync(0xffffffffu, h);
                if (h) {
                    int pos = base + __popc(mk & ltm);
                    if (pos < SCAP) { cv[pix][pos] = v; cid[pix][pos] = __float_as_int(l.w); }
                }
                base += __popc(mk);
            }
            cnt = base;
            if (cnt >= Kk && cnt <= SCAP) break;
            r = fminf(r * sqrtf(112.f / fmaxf((float)cnt, 2.f)), 3.1416f);
            thr = cosf(r);
        }
        cnts[s] = cnt;
        thrs[s] = thr;
    }
    __syncwarp();

    // exact top-64 via register cache + early-exit integer bisection on monotone key
#pragma unroll
    for (int s = 0; s < 2; s++) {
        int pix = 2 * w + s;
        int cnt = min(cnts[s], SCAP);
        float rv[6]; int rid[6]; unsigned kk[6];
        unsigned mx = 0u;
#pragma unroll
        for (int i = 0; i < 6; i++) {
            int t = lane + 32 * i;
            bool vld = t < cnt;
            rv[i]  = vld ? cv[pix][t] : 0.f;
            rid[i] = vld ? cid[pix][t] : 0x7FFFFFFF;
            kk[i]  = vld ? fkey(rv[i]) : 0u;   // 0 never counted (all real keys > 0)
            mx = max(mx, kk[i]);
        }
        // bisect on [fkey(thr), warp-max]; early-exit when count == 64 exactly
        unsigned lo = fkey(thrs[s]);
        unsigned hi = __reduce_max_sync(0xffffffffu, mx);
        bool exact = false;
        unsigned cutoff = 0u;
        while (lo < hi) {
            unsigned mid = lo + ((hi - lo + 1u) >> 1);
            int c = 0;
#pragma unroll
            for (int i = 0; i < 6; i++) c += (kk[i] >= mid);
            int tot = __reduce_add_sync(0xffffffffu, c);
            if (tot == Kk) { exact = true; cutoff = mid; break; }
            if (tot > Kk) lo = mid; else hi = mid - 1u;
        }
        unsigned T = lo;
        if (!exact) cutoff = T + 1u;   // collect strictly-greater, fill ties below
        // collect key >= cutoff (deterministic ballot order)
        int base = 0;
#pragma unroll
        for (int i = 0; i < 6; i++) {
            bool h = kk[i] >= cutoff;
            unsigned mk = __ballot_sync(0xffffffffu, h);
            if (h) {
                int pos = base + __popc(mk & ltm);
                swv[pix][pos] = rv[i]; swid[pix][pos] = rid[i];
            }
            base += __popc(mk);
        }
        if (!exact) {
            int cgt = base;          // < 64 by construction
            int need = Kk - cgt;
            int ntb = 0;
#pragma unroll
            for (int i = 0; i < 6; i++) {
                bool e = kk[i] == T;
                unsigned mk = __ballot_sync(0xffffffffu, e);
                if (e) {
                    int pos = ntb + __popc(mk & ltm);
                    cid[pix][pos] = rid[i];   // cv/cid rows now free scratch
                }
                ntb += __popc(mk);
            }
            float Tval = fkeyinv(T);
            for (int t = lane; t < ntb; t += 32) {
                int id = cid[pix][t];
                int rank = 0;
                for (int j = 0; j < ntb; j++) rank += (cid[pix][j] < id);
                if (rank < need) { swv[pix][cgt + rank] = Tval; swid[pix][cgt + rank] = id; }
            }
        }
    }
    __syncwarp();

    // attention MLP + softmax pool per pixel (warp-local, 2 logits per lane)
    const float4* __restrict__ los = g_los4 + b * Nn;
#pragma unroll
    for (int s = 0; s < 2; s++) {
        int pix = 2 * w + s;
        float v0 = swv[pix][lane], v1 = swv[pix][lane + 32];
        int   i0 = swid[pix][lane], i1 = swid[pix][lane + 32];
        float x0 = los[i0].w, x1 = los[i1].w;
        float d0 = acosf(fminf(1.f, fmaxf(-1.f, v0)));
        float d1 = acosf(fminf(1.f, fmaxf(-1.f, v1)));
        float l0 = sab2v, l1 = sab2v;
#pragma unroll
        for (int j = 0; j < 32; j++) {
            float h0 = fmaf(x0, sw1x[j], fmaf(d0, sw1d[j], sb1[j]));
            float h1 = fmaf(x1, sw1x[j], fmaf(d1, sw1d[j], sb1[j]));
            l0 = fmaf(fmaxf(h0, 0.f), sw2[j], l0);
            l1 = fmaf(fmaxf(h1, 0.f), sw2[j], l1);
        }
        float mx = fmaxf(l0, l1);
#pragma unroll
        for (int off = 16; off; off >>= 1) mx = fmaxf(mx, __shfl_xor_sync(0xffffffffu, mx, off));
        float e0 = __expf(l0 - mx), e1 = __expf(l1 - mx);
        float sm = e0 + e1;
        float wx = e0 * x0 + e1 * x1;
#pragma unroll
        for (int off = 16; off; off >>= 1) {
            sm += __shfl_xor_sync(0xffffffffu, sm, off);
            wx += __shfl_xor_sync(0xffffffffu, wx, off);
        }
        if (lane == 0) spool[pix] = wx / sm;
    }
    __syncthreads();

    // projection: 16 pixels x 64 features
    for (int i = tid; i < 16 * 64; i += 256) {
        int pix = i >> 6, c = i & 63;
        g_h0[(b * Mm + m0 + pix) * 64 + c] = fmaxf(fmaf(spool[pix], pw[c], pb[c]), 0.f);
    }
}

// ---------------- K3: GNN layer, 32-row tiles (768 blocks), two K=64 phases ----------------
// smem floats: sAT[64][33] @0 (2112), sW[64][64] @2112 (4096), sbias @6208, snbr(int)[256] @6272
#define GNN_SMEMF 6528
__global__ void k_gnn(const float* __restrict__ relw, const float* __restrict__ relb,
                      const float* __restrict__ rootw, int layer, int dir) {
    extern __shared__ float smbuf[];
    float* sAT   = smbuf;                 // [k][r], stride 33 (r < 32)
    float* sW    = smbuf + 2112;          // [k][c], stride 64
    float* sbias = smbuf + 6208;
    int*   snbr  = (int*)(smbuf + 6272);

    const float* hin  = dir ? g_h1 : g_h0;
    float*       hout = dir ? g_h0 : g_h1;

    int tid = threadIdx.x;
    int row0 = blockIdx.x * 32;
    int b = row0 / Mm;
    int m0 = row0 - b * Mm;

    for (int i = tid; i < 4096; i += 256) sW[i] = relw[layer * 4096 + i];
    if (tid < 64) sbias[tid] = relb[layer * 64 + tid];
    if (tid < 256) snbr[tid] = g_nbr[m0 * 8 + tid];
    __syncthreads();
    {
        int c = tid & 63, rq = tid >> 6;
        for (int rr = rq; rr < 32; rr += 4) {
            float a = 0.f;
#pragma unroll
            for (int j = 0; j < 8; j++) a += hin[(b * Mm + snbr[rr * 8 + j]) * 64 + c];
            sAT[c * 33 + rr] = a;
        }
    }
    __syncthreads();

    int tx = tid & 15, ty = tid >> 4;
    int r0 = ty * 2, c0 = tx * 4;
    float acc[2][4];
#pragma unroll
    for (int i = 0; i < 2; i++)
#pragma unroll
        for (int j = 0; j < 4; j++) acc[i][j] = sbias[c0 + j];

#pragma unroll 4
    for (int k = 0; k < 64; k++) {
        float a0 = sAT[k * 33 + r0];
        float a1 = sAT[k * 33 + r0 + 1];
        float4 wv = *(const float4*)&sW[k * 64 + c0];
        acc[0][0] = fmaf(a0, wv.x, acc[0][0]); acc[0][1] = fmaf(a0, wv.y, acc[0][1]);
        acc[0][2] = fmaf(a0, wv.z, acc[0][2]); acc[0][3] = fmaf(a0, wv.w, acc[0][3]);
        acc[1][0] = fmaf(a1, wv.x, acc[1][0]); acc[1][1] = fmaf(a1, wv.y, acc[1][1]);
        acc[1][2] = fmaf(a1, wv.z, acc[1][2]); acc[1][3] = fmaf(a1, wv.w, acc[1][3]);
    }
    __syncthreads();

    for (int i = tid; i < 4096; i += 256) sW[i] = rootw[layer * 4096 + i];
    for (int i = tid; i < 2048; i += 256) {
        int r = i >> 6, k = i & 63;
        sAT[k * 33 + r] = hin[row0 * 64 + i];
    }
    __syncthreads();

#pragma unroll 4
    for (int k = 0; k < 64; k++) {
        float a0 = sAT[k * 33 + r0];
        float a1 = sAT[k * 33 + r0 + 1];
        float4 wv = *(const float4*)&sW[k * 64 + c0];
        acc[0][0] = fmaf(a0, wv.x, acc[0][0]); acc[0][1] = fmaf(a0, wv.y, acc[0][1]);
        acc[0][2] = fmaf(a0, wv.z, acc[0][2]); acc[0][3] = fmaf(a0, wv.w, acc[0][3]);
        acc[1][0] = fmaf(a1, wv.x, acc[1][0]); acc[1][1] = fmaf(a1, wv.y, acc[1][1]);
        acc[1][2] = fmaf(a1, wv.z, acc[1][2]); acc[1][3] = fmaf(a1, wv.w, acc[1][3]);
    }

#pragma unroll
    for (int i = 0; i < 2; i++) {
        float4 o;
        o.x = fmaxf(acc[i][0], 0.f);
        o.y = fmaxf(acc[i][1], 0.f);
        o.z = fmaxf(acc[i][2], 0.f);
        o.w = fmaxf(acc[i][3], 0.f);
        *(float4*)&hout[(row0 + r0 + i) * 64 + c0] = o;
    }
}

// ---------------- K4a: partial mean-pool reduction ----------------
__global__ void k_red() {
    __shared__ float part[128];
    int tid = threadIdx.x;
    int blk = blockIdx.x;
    int b = blk / 96, seg = blk % 96;
    int c = tid & 63, half = tid >> 6;
    float a = 0.f;
    int mbase = seg * 128;
    for (int i = half; i < 128; i += 2)
        a += g_h1[(b * Mm + mbase + i) * 64 + c];
    part[tid] = a;
    __syncthreads();
    if (tid < 64) g_part[(b * 96 + seg) * 64 + c] = part[tid] + part[tid + 64];
}

// ---------------- K4b: final reduce + output MLP ----------------
__global__ void k_out(const float* __restrict__ ow1, const float* __restrict__ ob1,
                      const float* __restrict__ ow2, const float* __restrict__ ob2,
                      float* __restrict__ out) {
    __shared__ float sgf[64], shid[64];
    int tid = threadIdx.x;
    int b = blockIdx.x;
    if (tid < 64) {
        float a = 0.f;
        for (int s = 0; s < 96; s++) a += g_part[(b * 96 + s) * 64 + tid];
        sgf[tid] = a * (1.f / (float)Mm);
    }
    __syncthreads();
    if (tid < 64) {
        float a = ob1[tid];
        for (int k = 0; k < 64; k++) a = fmaf(sgf[k], ow1[k * 64 + tid], a);
        shid[tid] = fmaxf(a, 0.f);
    }
    __syncthreads();
    if (tid < NCc) {
        float a = ob2[tid];
        for (int k = 0; k < 64; k++) a = fmaf(shid[k], ow2[k * NCc + tid], a);
        out[b * NCc + tid] = a;
    }
}

// ---------------- launch ----------------
extern "C" void kernel_launch(void* const* d_in, const int* in_sizes, int n_in,
                              void* d_out, int out_size) {
    const float* xxx  = (const float*)d_in[0];
    const float* ptp  = (const float*)d_in[1];
    const float* aw1  = (const float*)d_in[2];
    const float* ab1  = (const float*)d_in[3];
    const float* aw2  = (const float*)d_in[4];
    const float* ab2  = (const float*)d_in[5];
    const float* pw   = (const float*)d_in[6];
    const float* pb   = (const float*)d_in[7];
    const float* relw = (const float*)d_in[8];
    const float* relb = (const float*)d_in[9];
    const float* rootw= (const float*)d_in[10];
    const float* ow1  = (const float*)d_in[11];
    const float* ob1  = (const float*)d_in[12];
    const float* ow2  = (const float*)d_in[13];
    const float* ob2  = (const float*)d_in[14];
    float* out = (float*)d_out;

    (void)in_sizes; (void)n_in; (void)out_size;

    k_pre<<<48, 256>>>(xxx, ptp);             // my idx 0 (harness pre-launches 2 -> overall 2)
    k_sort<<<3, 256>>>(xxx, ptp);             // my idx 1 -> overall 3
    k_knn<<<Mm / 16, 256>>>(ptp);             // my idx 2 -> overall 4
    k_samp<<<Bq * 768, 256>>>(ptp, aw1, ab1, aw2, ab2, pw, pb);  // my idx 3 -> overall 5 <- ncu

    const int SM3 = GNN_SMEMF * 4;
    cudaFuncSetAttribute(k_gnn, cudaFuncAttributeMaxDynamicSharedMemorySize, SM3);
    k_gnn<<<768, 256, SM3>>>(relw, relb, rootw, 0, 0); // g_h0 -> g_h1
    k_gnn<<<768, 256, SM3>>>(relw, relb, rootw, 1, 1); // g_h1 -> g_h0
    k_gnn<<<768, 256, SM3>>>(relw, relb, rootw, 2, 0); // g_h0 -> g_h1

    k_red<<<Bq * 96, 128>>>();
    k_out<<<Bq, 256>>>(ow1, ob1, ow2, ob2, out);
}